// round 4
// baseline (speedup 1.0000x reference)
#include <cuda_runtime.h>
#include <math.h>

// ---------------- problem constants ----------------
#define Bc   4
#define Nc   50000
#define BNc  (Bc * Nc)
#define Tc   12
#define Hc   32
#define H2c  64
#define Rc   64

#define NRM     0.4204482076268573f   /* 32^-0.25 */
#define RATIO   0.125f                /* 64^-0.5  */
#define EPSP    1e-4f
#define EPS_LN  1e-5f

#define PB         98                 /* kv partial blocks per batch */
#define CHUNK      512                /* nodes per kv block          */
#define TJ         32                 /* node tile in kv inner loop  */
#define DEN_CHUNKS 196                /* ceil(Nc/256)                */

// ---------------- f32x2 packed math (Blackwell) ----------------
__device__ __forceinline__ unsigned long long pk2(float a, float b) {
    unsigned long long r;
    asm("mov.b64 %0, {%1, %2};" : "=l"(r) : "f"(a), "f"(b));
    return r;
}
__device__ __forceinline__ void fma2(unsigned long long& d,
                                     unsigned long long a, unsigned long long b) {
    asm("fma.rn.f32x2 %0, %1, %2, %0;" : "+l"(d) : "l"(a), "l"(b));
}
__device__ __forceinline__ void upk2(float& lo, float& hi, unsigned long long v) {
    asm("mov.b64 {%0, %1}, %2;" : "=f"(lo), "=f"(hi) : "l"(v));
}

// ---------------- scratch ----------------
__device__ float    d_qp[Rc * Nc];
__device__ float    d_fk[Rc * Nc];
__device__ float    d_kp[Rc * Nc];
__device__ float    d_hnode[H2c * Nc];
__device__ float    d_neT[Hc * Nc];       // node_emb transposed [d][n]
__device__ float    d_ie[Hc * BNc];       // written by kB, read by kC
__device__ unsigned d_keymax;
__device__ float    d_kv[Bc][Rc * H2c];
__device__ float    d_denv[Rc];
__device__ float    d_kvpart[Bc][PB][Rc * H2c];
__device__ float    d_denpart[Rc][DEN_CHUNKS];

__global__ void kInit() { d_keymax = 0u; }

// ---------------- Stage A: per-node (b-independent) ----------------
__global__ void __launch_bounds__(128) kA(
    const float* __restrict__ node_emb,
    const float* __restrict__ w1, const float* __restrict__ b1,
    const float* __restrict__ w2, const float* __restrict__ b2,
    const float* __restrict__ rm1,
    const float* __restrict__ fc_w, const float* __restrict__ fc_b)
{
    __shared__ float s_w1[Hc * Hc], s_w2[Hc * Hc], s_rm[Rc * Hc], s_fr[H2c * Hc];
    __shared__ float s_b1[Hc], s_b2[Hc], s_fb[H2c];
    int tid = threadIdx.x;
    for (int i = tid; i < Hc * Hc; i += 128) { s_w1[i] = w1[i]; s_w2[i] = w2[i]; }
    for (int i = tid; i < Rc * Hc; i += 128) s_rm[i] = rm1[i];
    for (int i = tid; i < H2c * Hc; i += 128) {
        int o = i / Hc, d = i % Hc;
        s_fr[i] = fc_w[o * H2c + Hc + d];      // right half (node part)
    }
    if (tid < Hc)  { s_b1[tid] = b1[tid]; s_b2[tid] = b2[tid]; }
    if (tid < H2c) s_fb[tid] = fc_b[tid];
    __syncthreads();

    int n = blockIdx.x * 128 + tid;
    float kmaxdd = -3.0e38f;

    if (n < Nc) {
        float nd[Hc];
        #pragma unroll
        for (int d = 0; d < Hc; d++) nd[d] = node_emb[n * Hc + d];
        #pragma unroll
        for (int d = 0; d < Hc; d++) d_neT[d * Nc + n] = nd[d];

        float nv[Hc];

        // ---- queries: nv1 = node @ w1 + b1 ----
        #pragma unroll
        for (int h = 0; h < Hc; h++) {
            float a = s_b1[h];
            #pragma unroll
            for (int d = 0; d < Hc; d++) a += nd[d] * s_w1[h * Hc + d];
            nv[h] = a;
        }
        float diag = 0.f;
        #pragma unroll
        for (int h = 0; h < Hc; h++) diag += nv[h] * nv[h];
        diag *= 0.5f * NRM * NRM;

        float mx = -3.0e38f;
        for (int r = 0; r < Rc; r++) {
            float a = 0.f;
            #pragma unroll
            for (int h = 0; h < Hc; h++) a += nv[h] * s_rm[r * Hc + h];
            a *= NRM;
            mx = fmaxf(mx, a);
        }
        for (int r = 0; r < Rc; r++) {
            float a = 0.f;
            #pragma unroll
            for (int h = 0; h < Hc; h++) a += nv[h] * s_rm[r * Hc + h];
            a *= NRM;
            d_qp[r * Nc + n] = RATIO * (expf(a - diag - mx) + EPSP);
        }

        // ---- keys: nv2 = node @ w2 + b2 ----
        #pragma unroll
        for (int h = 0; h < Hc; h++) {
            float a = s_b2[h];
            #pragma unroll
            for (int d = 0; d < Hc; d++) a += nd[d] * s_w2[h * Hc + d];
            nv[h] = a;
        }
        float diagk = 0.f;
        #pragma unroll
        for (int h = 0; h < Hc; h++) diagk += nv[h] * nv[h];
        diagk *= 0.5f * NRM * NRM;

        for (int r = 0; r < Rc; r++) {
            float a = 0.f;
            #pragma unroll
            for (int h = 0; h < Hc; h++) a += nv[h] * s_rm[r * Hc + h];
            a *= NRM;
            d_fk[r * Nc + n] = a - diagk;
            kmaxdd = fmaxf(kmaxdd, a);
        }

        // ---- hnode = node @ fc_w[:,32:64] + fc_b ----
        for (int o = 0; o < H2c; o++) {
            float a = s_fb[o];
            #pragma unroll
            for (int d = 0; d < Hc; d++) a += nd[d] * s_fr[o * Hc + d];
            d_hnode[o * Nc + n] = a;
        }
    }

    // order-invariant (deterministic) global max
    #pragma unroll
    for (int off = 16; off; off >>= 1)
        kmaxdd = fmaxf(kmaxdd, __shfl_xor_sync(0xffffffffu, kmaxdd, off));
    if ((tid & 31) == 0) {
        unsigned bits = __float_as_uint(kmaxdd);
        unsigned enc = (bits & 0x80000000u) ? ~bits : (bits | 0x80000000u);
        atomicMax(&d_keymax, enc);
    }
}

// ---------------- kp = ratio*(exp(fk - M) + eps), den partials ----------------
__global__ void __launch_bounds__(256) kKP()
{
    int r = blockIdx.y;
    int n = blockIdx.x * 256 + threadIdx.x;
    unsigned enc = d_keymax;
    float M = (enc & 0x80000000u) ? __uint_as_float(enc ^ 0x80000000u)
                                  : __uint_as_float(~enc);
    float v = 0.f;
    if (n < Nc) {
        v = RATIO * (expf(d_fk[r * Nc + n] - M) + EPSP);
        d_kp[r * Nc + n] = v;
    }
    __shared__ float red[256];
    red[threadIdx.x] = v;
    __syncthreads();
    #pragma unroll
    for (int s = 128; s; s >>= 1) {
        if (threadIdx.x < s) red[threadIdx.x] += red[threadIdx.x + s];
        __syncthreads();
    }
    if (threadIdx.x == 0) d_denpart[r][blockIdx.x] = red[0];
}

// ---------------- Stage B: fused ie/h0 + kv partials ----------------
__global__ void __launch_bounds__(256) kB(
    const float* __restrict__ x,
    const float* __restrict__ w_input, const float* __restrict__ b_input,
    const float* __restrict__ fc_w)
{
    __shared__ float s_wi[Hc * Tc], s_bi[Hc], s_fl[H2c * Hc];
    __shared__ float s_x[TJ][37];
    __shared__ float s_ie[TJ][33];
    __shared__ float s_kp[TJ][Rc + 1];
    __shared__ float s_v[TJ][H2c + 4];

    int b = blockIdx.y, p = blockIdx.x;
    int n0 = p * CHUNK;
    int n1 = min(n0 + CHUNK, Nc);
    int tid = threadIdx.x;
    int r  = tid & 63;
    int cg = tid >> 6;                 // c base = cg*16 in accumulate
    int j5 = tid & 31;                 // node index in ie/h0 steps
    int hq = tid >> 5;                 // 0..7

    for (int i = tid; i < Hc * Tc; i += 256) s_wi[i] = w_input[i];
    for (int i = tid; i < H2c * Hc; i += 256) {
        int o = i / Hc, d = i % Hc;
        s_fl[i] = fc_w[o * H2c + d];   // left half (ie part)
    }
    if (tid < Hc) s_bi[tid] = b_input[tid];

    unsigned long long acc2[8];
    #pragma unroll
    for (int q = 0; q < 8; q++) acc2[q] = 0ull;

    for (int jt = n0; jt < n1; jt += TJ) {
        int cnt = min(TJ, n1 - jt);

        // --- stage x rows (coalesced float4) ---
        const float4* xp4 = (const float4*)(x + ((size_t)b * Nc + jt) * 36);
        for (int i = tid; i < cnt * 9; i += 256) {
            float4 v = xp4[i];
            int e = i * 4, r0 = e / 36, c0 = e - r0 * 36;
            int r1 = r0, c1 = c0 + 1; if (c1 >= 36) { r1++; c1 -= 36; }
            int r2 = r0, c2 = c0 + 2; if (c2 >= 36) { r2++; c2 -= 36; }
            int r3 = r0, c3 = c0 + 3; if (c3 >= 36) { r3++; c3 -= 36; }
            s_x[r0][c0] = v.x; s_x[r1][c1] = v.y;
            s_x[r2][c2] = v.z; s_x[r3][c3] = v.w;
        }
        // --- stage kp ---
        for (int k = tid; k < Rc * TJ; k += 256) {
            int rr = k / TJ, j = k % TJ;
            s_kp[j][rr] = (j < cnt) ? d_kp[rr * Nc + jt + j] : 0.f;
        }
        __syncthreads();

        // --- ie for this tile (thread: node j5, 4 h's) ---
        if (j5 < cnt) {
            #pragma unroll
            for (int q = 0; q < 4; q++) {
                int h = hq * 4 + q;
                float a = s_bi[h];
                #pragma unroll
                for (int t = 0; t < Tc; t++) a += s_x[j5][t * 3] * s_wi[h * Tc + t];
                s_ie[j5][h] = a;
                d_ie[(size_t)h * BNc + (size_t)b * Nc + jt + j5] = a;
            }
        }
        __syncthreads();

        // --- h0 = relu(ie @ fcwL + hnode) into s_v ---
        #pragma unroll
        for (int q = 0; q < 8; q++) {
            int c = hq * 8 + q;
            float a = 0.f;
            if (j5 < cnt) {
                a = d_hnode[c * Nc + jt + j5];
                #pragma unroll
                for (int d = 0; d < Hc; d++) a += s_ie[j5][d] * s_fl[c * Hc + d];
                a = fmaxf(a, 0.f);
            }
            s_v[j5][c] = a;
        }
        __syncthreads();

        // --- rank-1 accumulate (f32x2) ---
        #pragma unroll 2
        for (int j = 0; j < TJ; j++) {
            float kpv = s_kp[j][r];
            unsigned long long q2 = pk2(kpv, kpv);
            const float4* vp = (const float4*)&s_v[j][cg * 16];
            #pragma unroll
            for (int q = 0; q < 4; q++) {
                float4 v4 = vp[q];
                fma2(acc2[q * 2 + 0], q2, pk2(v4.x, v4.y));
                fma2(acc2[q * 2 + 1], q2, pk2(v4.z, v4.w));
            }
        }
        __syncthreads();
    }

    float accf[16];
    #pragma unroll
    for (int q = 0; q < 8; q++) upk2(accf[q * 2], accf[q * 2 + 1], acc2[q]);
    float* dst = &d_kvpart[b][p][r * H2c + cg * 16];
    #pragma unroll
    for (int q = 0; q < 4; q++)
        ((float4*)dst)[q] = make_float4(accf[q * 4 + 0], accf[q * 4 + 1],
                                        accf[q * 4 + 2], accf[q * 4 + 3]);
}

// ---------------- reduce kv + den partials ----------------
__global__ void __launch_bounds__(256) kB2()
{
    int idx = blockIdx.x * 256 + threadIdx.x;
    if (idx < Bc * Rc * H2c) {
        int b = idx / (Rc * H2c), rc = idx % (Rc * H2c);
        float s = 0.f;
        for (int p = 0; p < PB; p++) s += d_kvpart[b][p][rc];
        d_kv[b][rc] = s;
    } else if (idx < Bc * Rc * H2c + Rc) {
        int r = idx - Bc * Rc * H2c;
        float s = 0.f;
        for (int k = 0; k < DEN_CHUNKS; k++) s += d_denpart[r][k];
        d_denv[r] = s;
    }
}

// ---------------- Stage C: streaming qp (f32x2 num), residual/LN/out GEMM ----------------
__global__ void __launch_bounds__(128) kC(
    const float* __restrict__ ln_g, const float* __restrict__ ln_b,
    const float* __restrict__ w_reg, const float* __restrict__ b_reg,
    float* __restrict__ out)
{
    int b = blockIdx.y;
    __shared__ float4 s_kv4[Rc * 16];
    __shared__ float4 s_wr4[12 * 32];
    __shared__ float  s_den[Rc], s_g[H2c], s_be[H2c], s_br[12];
    int tid = threadIdx.x;
    {
        const float4* kvsrc = (const float4*)&d_kv[b][0];
        for (int i = tid; i < Rc * 16; i += 128) s_kv4[i] = kvsrc[i];
        const float4* wrsrc = (const float4*)w_reg;
        for (int i = tid; i < 12 * 32; i += 128) s_wr4[i] = wrsrc[i];
    }
    if (tid < Rc)  s_den[tid] = d_denv[tid];
    if (tid < H2c) { s_g[tid] = ln_g[tid]; s_be[tid] = ln_b[tid]; }
    if (tid < 12)  s_br[tid] = b_reg[tid];
    __syncthreads();

    int n = blockIdx.x * 128 + tid;
    if (n >= Nc) return;
    int bn = b * Nc + n;

    unsigned long long h2[32];
    #pragma unroll
    for (int c = 0; c < 32; c++) h2[c] = 0ull;
    float den = 0.f;

    #pragma unroll 4
    for (int r = 0; r < Rc; r++) {
        float q = d_qp[r * Nc + n];
        den += q * s_den[r];
        unsigned long long q2 = pk2(q, q);
        const float4* kvp = &s_kv4[r * 16];
        #pragma unroll
        for (int c4 = 0; c4 < 16; c4++) {
            float4 v = kvp[c4];
            fma2(h2[c4 * 2 + 0], q2, pk2(v.x, v.y));
            fma2(h2[c4 * 2 + 1], q2, pk2(v.z, v.w));
        }
    }

    float h[H2c];
    #pragma unroll
    for (int c = 0; c < 32; c++) upk2(h[c * 2], h[c * 2 + 1], h2[c]);

    float inv = 1.f / den;
    float outr[12];
    #pragma unroll
    for (int o = 0; o < 12; o++) outr[o] = s_br[o];

    float mu = 0.f;
    // ie part (c = 0..31)
    #pragma unroll
    for (int c4 = 0; c4 < 8; c4++) {
        float v0 = d_ie[(size_t)(c4 * 4 + 0) * BNc + bn];
        float v1 = d_ie[(size_t)(c4 * 4 + 1) * BNc + bn];
        float v2 = d_ie[(size_t)(c4 * 4 + 2) * BNc + bn];
        float v3 = d_ie[(size_t)(c4 * 4 + 3) * BNc + bn];
        h[c4 * 4 + 0] = h[c4 * 4 + 0] * inv + v0; mu += h[c4 * 4 + 0];
        h[c4 * 4 + 1] = h[c4 * 4 + 1] * inv + v1; mu += h[c4 * 4 + 1];
        h[c4 * 4 + 2] = h[c4 * 4 + 2] * inv + v2; mu += h[c4 * 4 + 2];
        h[c4 * 4 + 3] = h[c4 * 4 + 3] * inv + v3; mu += h[c4 * 4 + 3];
        float xv0 = fmaxf(v0, 0.f), xv1 = fmaxf(v1, 0.f);
        float xv2 = fmaxf(v2, 0.f), xv3 = fmaxf(v3, 0.f);
        #pragma unroll
        for (int o = 0; o < 12; o++) {
            float4 w = s_wr4[o * 32 + c4];
            outr[o] += xv0 * w.x + xv1 * w.y + xv2 * w.z + xv3 * w.w;
        }
    }
    // node part (c = 32..63)
    #pragma unroll
    for (int c4 = 8; c4 < 16; c4++) {
        float v0 = d_neT[(c4 * 4 + 0 - Hc) * Nc + n];
        float v1 = d_neT[(c4 * 4 + 1 - Hc) * Nc + n];
        float v2 = d_neT[(c4 * 4 + 2 - Hc) * Nc + n];
        float v3 = d_neT[(c4 * 4 + 3 - Hc) * Nc + n];
        h[c4 * 4 + 0] = h[c4 * 4 + 0] * inv + v0; mu += h[c4 * 4 + 0];
        h[c4 * 4 + 1] = h[c4 * 4 + 1] * inv + v1; mu += h[c4 * 4 + 1];
        h[c4 * 4 + 2] = h[c4 * 4 + 2] * inv + v2; mu += h[c4 * 4 + 2];
        h[c4 * 4 + 3] = h[c4 * 4 + 3] * inv + v3; mu += h[c4 * 4 + 3];
        float xv0 = fmaxf(v0, 0.f), xv1 = fmaxf(v1, 0.f);
        float xv2 = fmaxf(v2, 0.f), xv3 = fmaxf(v3, 0.f);
        #pragma unroll
        for (int o = 0; o < 12; o++) {
            float4 w = s_wr4[o * 32 + c4];
            outr[o] += xv0 * w.x + xv1 * w.y + xv2 * w.z + xv3 * w.w;
        }
    }

    mu *= (1.f / H2c);
    float var = 0.f;
    #pragma unroll
    for (int c = 0; c < H2c; c++) { float d0 = h[c] - mu; var += d0 * d0; }
    var *= (1.f / H2c);
    float rstd = rsqrtf(var + EPS_LN);
    #pragma unroll
    for (int c = 0; c < H2c; c++)
        h[c] = fmaxf((h[c] - mu) * rstd * s_g[c] + s_be[c], 0.f);

    #pragma unroll
    for (int c4 = 0; c4 < 16; c4++) {
        float h0v = h[c4 * 4 + 0], h1v = h[c4 * 4 + 1];
        float h2v = h[c4 * 4 + 2], h3v = h[c4 * 4 + 3];
        #pragma unroll
        for (int o = 0; o < 12; o++) {
            float4 w = s_wr4[o * 32 + 16 + c4];
            outr[o] += h0v * w.x + h1v * w.y + h2v * w.z + h3v * w.w;
        }
    }

    float* op = out + (size_t)bn * 12;
    #pragma unroll
    for (int o = 0; o < 12; o++) op[o] = outr[o];
}

// ---------------- launch ----------------
extern "C" void kernel_launch(void* const* d_in, const int* in_sizes, int n_in,
                              void* d_out, int out_size)
{
    (void)in_sizes; (void)n_in; (void)out_size;
    const float* x        = (const float*)d_in[0];
    const float* node_emb = (const float*)d_in[1];
    const float* w_input  = (const float*)d_in[4];
    const float* b_input  = (const float*)d_in[5];
    const float* w1       = (const float*)d_in[6];
    const float* b1       = (const float*)d_in[7];
    const float* w2       = (const float*)d_in[8];
    const float* b2       = (const float*)d_in[9];
    const float* fc_w     = (const float*)d_in[14];
    const float* fc_b     = (const float*)d_in[15];
    const float* ln_g     = (const float*)d_in[18];
    const float* ln_b     = (const float*)d_in[19];
    const float* w_reg    = (const float*)d_in[22];
    const float* b_reg    = (const float*)d_in[23];
    const float* rm1      = (const float*)d_in[24];
    float* out = (float*)d_out;

    kInit<<<1, 1>>>();
    kA<<<(Nc + 127) / 128, 128>>>(node_emb, w1, b1, w2, b2, rm1, fc_w, fc_b);
    kKP<<<dim3(DEN_CHUNKS, Rc), 256>>>();
    kB<<<dim3(PB, Bc), 256>>>(x, w_input, b_input, fc_w);
    kB2<<<(Bc * Rc * H2c + Rc + 255) / 256, 256>>>();
    kC<<<dim3((Nc + 127) / 128, Bc), 128>>>(ln_g, ln_b, w_reg, b_reg, out);
}

// round 5
// speedup vs baseline: 1.0817x; 1.0817x over previous
#include <cuda_runtime.h>
#include <math.h>

// ---------------- problem constants ----------------
#define Bc   4
#define Nc   50000
#define BNc  (Bc * Nc)
#define Tc   12
#define Hc   32
#define H2c  64
#define Rc   64

#define NRM     0.4204482076268573f   /* 32^-0.25 */
#define RATIO   0.125f                /* 64^-0.5  */
#define EPSP    1e-4f
#define EPS_LN  1e-5f

#define PB         98                 /* kv partial blocks per batch */
#define CHUNK      512                /* nodes per kv block          */
#define TJ         32                 /* node tile in kv inner loop  */

// ---------------- f32x2 packed math (Blackwell) ----------------
__device__ __forceinline__ unsigned long long pk2(float a, float b) {
    unsigned long long r;
    asm("mov.b64 %0, {%1, %2};" : "=l"(r) : "f"(a), "f"(b));
    return r;
}
__device__ __forceinline__ void fma2(unsigned long long& d,
                                     unsigned long long a, unsigned long long b) {
    asm("fma.rn.f32x2 %0, %1, %2, %0;" : "+l"(d) : "l"(a), "l"(b));
}
__device__ __forceinline__ void upk2(float& lo, float& hi, unsigned long long v) {
    asm("mov.b64 {%0, %1}, %2;" : "=f"(lo), "=f"(hi) : "l"(v));
}

// ---------------- scratch ----------------
__device__ float    d_qp[Rc * Nc];
__device__ float    d_fk[Rc * Nc];
__device__ float    d_hnode[H2c * Nc];
__device__ float    d_neT[Hc * Nc];       // node_emb transposed [d][n]
__device__ float    d_h0[H2c * BNc];      // v = relu(xc @ fc_w + fc_b)
__device__ float    d_ie[Hc * BNc];
__device__ unsigned d_keymax;
__device__ float    d_kv[Bc][Rc * H2c];
__device__ float    d_denv[Rc];
__device__ float    d_kvpart[Bc][PB][Rc * H2c];
__device__ float    d_denpart[Rc][PB];

__global__ void kInit() { d_keymax = 0u; }

__device__ __forceinline__ float decode_max(unsigned enc) {
    return (enc & 0x80000000u) ? __uint_as_float(enc ^ 0x80000000u)
                               : __uint_as_float(~enc);
}

// ---------------- Stage A: per-node (b-independent) ----------------
__global__ void __launch_bounds__(128) kA(
    const float* __restrict__ node_emb,
    const float* __restrict__ w1, const float* __restrict__ b1,
    const float* __restrict__ w2, const float* __restrict__ b2,
    const float* __restrict__ rm1,
    const float* __restrict__ fc_w, const float* __restrict__ fc_b)
{
    __shared__ float s_w1[Hc * Hc], s_w2[Hc * Hc], s_rm[Rc * Hc], s_fr[H2c * Hc];
    __shared__ float s_b1[Hc], s_b2[Hc], s_fb[H2c];
    int tid = threadIdx.x;
    for (int i = tid; i < Hc * Hc; i += 128) { s_w1[i] = w1[i]; s_w2[i] = w2[i]; }
    for (int i = tid; i < Rc * Hc; i += 128) s_rm[i] = rm1[i];
    for (int i = tid; i < H2c * Hc; i += 128) {
        int o = i / Hc, d = i % Hc;
        s_fr[i] = fc_w[o * H2c + Hc + d];      // right half (node part)
    }
    if (tid < Hc)  { s_b1[tid] = b1[tid]; s_b2[tid] = b2[tid]; }
    if (tid < H2c) s_fb[tid] = fc_b[tid];
    __syncthreads();

    int n = blockIdx.x * 128 + tid;
    float kmaxdd = -3.0e38f;

    if (n < Nc) {
        float nd[Hc];
        #pragma unroll
        for (int d = 0; d < Hc; d++) nd[d] = node_emb[n * Hc + d];
        #pragma unroll
        for (int d = 0; d < Hc; d++) d_neT[d * Nc + n] = nd[d];

        float nv[Hc];

        // ---- queries: nv1 = node @ w1 + b1 ----
        #pragma unroll
        for (int h = 0; h < Hc; h++) {
            float a = s_b1[h];
            #pragma unroll
            for (int d = 0; d < Hc; d++) a += nd[d] * s_w1[h * Hc + d];
            nv[h] = a;
        }
        float diag = 0.f;
        #pragma unroll
        for (int h = 0; h < Hc; h++) diag += nv[h] * nv[h];
        diag *= 0.5f * NRM * NRM;

        float mx = -3.0e38f;
        for (int r = 0; r < Rc; r++) {
            float a = 0.f;
            #pragma unroll
            for (int h = 0; h < Hc; h++) a += nv[h] * s_rm[r * Hc + h];
            a *= NRM;
            mx = fmaxf(mx, a);
        }
        for (int r = 0; r < Rc; r++) {
            float a = 0.f;
            #pragma unroll
            for (int h = 0; h < Hc; h++) a += nv[h] * s_rm[r * Hc + h];
            a *= NRM;
            d_qp[r * Nc + n] = RATIO * (expf(a - diag - mx) + EPSP);
        }

        // ---- keys: nv2 = node @ w2 + b2 ----
        #pragma unroll
        for (int h = 0; h < Hc; h++) {
            float a = s_b2[h];
            #pragma unroll
            for (int d = 0; d < Hc; d++) a += nd[d] * s_w2[h * Hc + d];
            nv[h] = a;
        }
        float diagk = 0.f;
        #pragma unroll
        for (int h = 0; h < Hc; h++) diagk += nv[h] * nv[h];
        diagk *= 0.5f * NRM * NRM;

        for (int r = 0; r < Rc; r++) {
            float a = 0.f;
            #pragma unroll
            for (int h = 0; h < Hc; h++) a += nv[h] * s_rm[r * Hc + h];
            a *= NRM;
            d_fk[r * Nc + n] = a - diagk;
            kmaxdd = fmaxf(kmaxdd, a);
        }

        // ---- hnode = node @ fc_w[:,32:64] + fc_b ----
        for (int o = 0; o < H2c; o++) {
            float a = s_fb[o];
            #pragma unroll
            for (int d = 0; d < Hc; d++) a += nd[d] * s_fr[o * Hc + d];
            d_hnode[o * Nc + n] = a;
        }
    }

    // order-invariant (deterministic) global max
    #pragma unroll
    for (int off = 16; off; off >>= 1)
        kmaxdd = fmaxf(kmaxdd, __shfl_xor_sync(0xffffffffu, kmaxdd, off));
    if ((tid & 31) == 0) {
        unsigned bits = __float_as_uint(kmaxdd);
        unsigned enc = (bits & 0x80000000u) ? ~bits : (bits | 0x80000000u);
        atomicMax(&d_keymax, enc);
    }
}

// ---------------- Stage V: input_emb + v = relu(ie@fcwL + hnode), f32x2 ----------------
__global__ void __launch_bounds__(128) kV(
    const float* __restrict__ x,
    const float* __restrict__ w_input, const float* __restrict__ b_input,
    const float* __restrict__ fc_w)
{
    __shared__ float s_wi[Hc * Tc], s_bi[Hc], s_fl[H2c * Hc];
    int tid = threadIdx.x;
    for (int i = tid; i < Hc * Tc; i += 128) s_wi[i] = w_input[i];
    for (int i = tid; i < H2c * Hc; i += 128) {
        int o = i / Hc, d = i % Hc;
        s_fl[i] = fc_w[o * H2c + d];          // left half (ie part)
    }
    if (tid < Hc) s_bi[tid] = b_input[tid];
    __syncthreads();

    int bn = blockIdx.x * 128 + tid;
    if (bn >= BNc) return;
    int n = bn % Nc;

    float xt[Tc];
    const float* xp = x + (size_t)bn * (Tc * 3);
    #pragma unroll
    for (int t = 0; t < Tc; t++) xt[t] = xp[t * 3];

    unsigned long long ie2[16];
    #pragma unroll
    for (int hp = 0; hp < 16; hp++) {
        int h0i = 2 * hp, h1i = 2 * hp + 1;
        float a0 = s_bi[h0i], a1 = s_bi[h1i];
        #pragma unroll
        for (int t = 0; t < Tc; t++) {
            a0 += xt[t] * s_wi[h0i * Tc + t];
            a1 += xt[t] * s_wi[h1i * Tc + t];
        }
        d_ie[(size_t)h0i * BNc + bn] = a0;
        d_ie[(size_t)h1i * BNc + bn] = a1;
        ie2[hp] = pk2(a0, a1);
    }

    for (int o = 0; o < H2c; o++) {
        unsigned long long acc_a = 0ull, acc_b = 0ull;
        const float4* fl4 = (const float4*)&s_fl[o * Hc];
        #pragma unroll
        for (int k = 0; k < 8; k++) {
            float4 f = fl4[k];
            fma2(acc_a, ie2[2 * k + 0], pk2(f.x, f.y));
            fma2(acc_b, ie2[2 * k + 1], pk2(f.z, f.w));
        }
        float l0, hi0, l1, hi1;
        upk2(l0, hi0, acc_a);
        upk2(l1, hi1, acc_b);
        float a = d_hnode[o * Nc + n] + ((l0 + hi0) + (l1 + hi1));
        d_h0[(size_t)o * BNc + bn] = fmaxf(a, 0.f);
    }
}

// ---------------- Stage B: kv partials + inline exp(kp) + den (b==0) ----------------
__global__ void __launch_bounds__(256) kB()
{
    int b = blockIdx.y, p = blockIdx.x;
    int n0 = p * CHUNK;
    int n1 = min(n0 + CHUNK, Nc);
    int tid = threadIdx.x;
    int r = tid & 63;
    int cg = tid >> 6;                  // c base = cg*16

    __shared__ float s_kp[TJ][Rc + 1];  // [j][r]
    __shared__ float s_v[TJ][H2c + 4];  // [j][c]

    float M = decode_max(d_keymax);

    unsigned long long acc2[8];
    #pragma unroll
    for (int q = 0; q < 8; q++) acc2[q] = 0ull;
    float dreg = 0.f;

    for (int jt = n0; jt < n1; jt += TJ) {
        int cnt = min(TJ, n1 - jt);
        for (int k = tid; k < Rc * TJ; k += 256) {
            int rr = k >> 5, j = k & 31;
            float v = 0.f;
            if (j < cnt)
                v = RATIO * (__expf(d_fk[rr * Nc + jt + j] - M) + EPSP);
            s_kp[j][rr] = v;
        }
        for (int k = tid; k < H2c * TJ; k += 256) {
            int c = k >> 5, j = k & 31;
            s_v[j][c] = (j < cnt) ? d_h0[(size_t)c * BNc + (size_t)b * Nc + jt + j] : 0.f;
        }
        __syncthreads();

        if (b == 0 && tid < 64) {
            #pragma unroll 8
            for (int j = 0; j < TJ; j++) dreg += s_kp[j][tid];
        }

        #pragma unroll 2
        for (int j = 0; j < TJ; j++) {
            float kpv = s_kp[j][r];
            unsigned long long q2 = pk2(kpv, kpv);
            const float4* vp = (const float4*)&s_v[j][cg * 16];
            #pragma unroll
            for (int q = 0; q < 4; q++) {
                float4 v4 = vp[q];
                fma2(acc2[q * 2 + 0], q2, pk2(v4.x, v4.y));
                fma2(acc2[q * 2 + 1], q2, pk2(v4.z, v4.w));
            }
        }
        __syncthreads();
    }

    float accf[16];
    #pragma unroll
    for (int q = 0; q < 8; q++) upk2(accf[q * 2], accf[q * 2 + 1], acc2[q]);
    float* dst = &d_kvpart[b][p][r * H2c + cg * 16];
    #pragma unroll
    for (int q = 0; q < 4; q++)
        ((float4*)dst)[q] = make_float4(accf[q * 4 + 0], accf[q * 4 + 1],
                                        accf[q * 4 + 2], accf[q * 4 + 3]);
    if (b == 0 && tid < 64) d_denpart[tid][p] = dreg;
}

// ---------------- reduce kv + den partials ----------------
__global__ void __launch_bounds__(256) kB2()
{
    int idx = blockIdx.x * 256 + threadIdx.x;
    if (idx < Bc * Rc * H2c) {
        int b = idx / (Rc * H2c), rc = idx % (Rc * H2c);
        float s = 0.f;
        for (int p = 0; p < PB; p++) s += d_kvpart[b][p][rc];
        d_kv[b][rc] = s;
    } else if (idx < Bc * Rc * H2c + Rc) {
        int r = idx - Bc * Rc * H2c;
        float s = 0.f;
        for (int p = 0; p < PB; p++) s += d_denpart[r][p];
        d_denv[r] = s;
    }
}

// ---------------- Stage C: batch-looped; streaming qp (f32x2), LN, out GEMM ----------------
__global__ void __launch_bounds__(128) kC(
    const float* __restrict__ ln_g, const float* __restrict__ ln_b,
    const float* __restrict__ w_reg, const float* __restrict__ b_reg,
    float* __restrict__ out)
{
    __shared__ float4 s_kv4[Rc * 16];
    __shared__ float4 s_wr4[12 * 32];
    __shared__ float  s_den[Rc], s_g[H2c], s_be[H2c], s_br[12];
    int tid = threadIdx.x;
    {
        const float4* wrsrc = (const float4*)w_reg;
        for (int i = tid; i < 12 * 32; i += 128) s_wr4[i] = wrsrc[i];
    }
    if (tid < Rc)  s_den[tid] = d_denv[tid];
    if (tid < H2c) { s_g[tid] = ln_g[tid]; s_be[tid] = ln_b[tid]; }
    if (tid < 12)  s_br[tid] = b_reg[tid];

    int n = blockIdx.x * 128 + tid;
    bool valid = (n < Nc);

    for (int b = 0; b < Bc; b++) {
        __syncthreads();
        {
            const float4* kvsrc = (const float4*)&d_kv[b][0];
            for (int i = tid; i < Rc * 16; i += 128) s_kv4[i] = kvsrc[i];
        }
        __syncthreads();
        if (!valid) continue;
        int bn = b * Nc + n;

        unsigned long long h2[32];
        #pragma unroll
        for (int c = 0; c < 32; c++) h2[c] = 0ull;
        float den = 0.f;

        #pragma unroll 4
        for (int r = 0; r < Rc; r++) {
            float q = d_qp[r * Nc + n];
            den += q * s_den[r];
            unsigned long long q2 = pk2(q, q);
            const float4* kvp = &s_kv4[r * 16];
            #pragma unroll
            for (int c4 = 0; c4 < 16; c4++) {
                float4 v = kvp[c4];
                fma2(h2[c4 * 2 + 0], q2, pk2(v.x, v.y));
                fma2(h2[c4 * 2 + 1], q2, pk2(v.z, v.w));
            }
        }

        float h[H2c];
        #pragma unroll
        for (int c = 0; c < 32; c++) upk2(h[c * 2], h[c * 2 + 1], h2[c]);

        float inv = 1.f / den;
        float outr[12];
        #pragma unroll
        for (int o = 0; o < 12; o++) outr[o] = s_br[o];

        float mu = 0.f;
        // ie part (c = 0..31)
        #pragma unroll
        for (int c4 = 0; c4 < 8; c4++) {
            float v0 = d_ie[(size_t)(c4 * 4 + 0) * BNc + bn];
            float v1 = d_ie[(size_t)(c4 * 4 + 1) * BNc + bn];
            float v2 = d_ie[(size_t)(c4 * 4 + 2) * BNc + bn];
            float v3 = d_ie[(size_t)(c4 * 4 + 3) * BNc + bn];
            h[c4 * 4 + 0] = h[c4 * 4 + 0] * inv + v0; mu += h[c4 * 4 + 0];
            h[c4 * 4 + 1] = h[c4 * 4 + 1] * inv + v1; mu += h[c4 * 4 + 1];
            h[c4 * 4 + 2] = h[c4 * 4 + 2] * inv + v2; mu += h[c4 * 4 + 2];
            h[c4 * 4 + 3] = h[c4 * 4 + 3] * inv + v3; mu += h[c4 * 4 + 3];
            float xv0 = fmaxf(v0, 0.f), xv1 = fmaxf(v1, 0.f);
            float xv2 = fmaxf(v2, 0.f), xv3 = fmaxf(v3, 0.f);
            #pragma unroll
            for (int o = 0; o < 12; o++) {
                float4 w = s_wr4[o * 32 + c4];
                outr[o] += xv0 * w.x + xv1 * w.y + xv2 * w.z + xv3 * w.w;
            }
        }
        // node part (c = 32..63)
        #pragma unroll
        for (int c4 = 8; c4 < 16; c4++) {
            float v0 = d_neT[(c4 * 4 + 0 - Hc) * Nc + n];
            float v1 = d_neT[(c4 * 4 + 1 - Hc) * Nc + n];
            float v2 = d_neT[(c4 * 4 + 2 - Hc) * Nc + n];
            float v3 = d_neT[(c4 * 4 + 3 - Hc) * Nc + n];
            h[c4 * 4 + 0] = h[c4 * 4 + 0] * inv + v0; mu += h[c4 * 4 + 0];
            h[c4 * 4 + 1] = h[c4 * 4 + 1] * inv + v1; mu += h[c4 * 4 + 1];
            h[c4 * 4 + 2] = h[c4 * 4 + 2] * inv + v2; mu += h[c4 * 4 + 2];
            h[c4 * 4 + 3] = h[c4 * 4 + 3] * inv + v3; mu += h[c4 * 4 + 3];
            float xv0 = fmaxf(v0, 0.f), xv1 = fmaxf(v1, 0.f);
            float xv2 = fmaxf(v2, 0.f), xv3 = fmaxf(v3, 0.f);
            #pragma unroll
            for (int o = 0; o < 12; o++) {
                float4 w = s_wr4[o * 32 + c4];
                outr[o] += xv0 * w.x + xv1 * w.y + xv2 * w.z + xv3 * w.w;
            }
        }

        mu *= (1.f / H2c);
        float var = 0.f;
        #pragma unroll
        for (int c = 0; c < H2c; c++) { float d0 = h[c] - mu; var += d0 * d0; }
        var *= (1.f / H2c);
        float rstd = rsqrtf(var + EPS_LN);
        #pragma unroll
        for (int c = 0; c < H2c; c++)
            h[c] = fmaxf((h[c] - mu) * rstd * s_g[c] + s_be[c], 0.f);

        #pragma unroll
        for (int c4 = 0; c4 < 16; c4++) {
            float h0v = h[c4 * 4 + 0], h1v = h[c4 * 4 + 1];
            float h2v = h[c4 * 4 + 2], h3v = h[c4 * 4 + 3];
            #pragma unroll
            for (int o = 0; o < 12; o++) {
                float4 w = s_wr4[o * 32 + 16 + c4];
                outr[o] += h0v * w.x + h1v * w.y + h2v * w.z + h3v * w.w;
            }
        }

        float* op = out + (size_t)bn * 12;
        #pragma unroll
        for (int o = 0; o < 12; o++) op[o] = outr[o];
    }
}

// ---------------- launch ----------------
extern "C" void kernel_launch(void* const* d_in, const int* in_sizes, int n_in,
                              void* d_out, int out_size)
{
    (void)in_sizes; (void)n_in; (void)out_size;
    const float* x        = (const float*)d_in[0];
    const float* node_emb = (const float*)d_in[1];
    const float* w_input  = (const float*)d_in[4];
    const float* b_input  = (const float*)d_in[5];
    const float* w1       = (const float*)d_in[6];
    const float* b1       = (const float*)d_in[7];
    const float* w2       = (const float*)d_in[8];
    const float* b2       = (const float*)d_in[9];
    const float* fc_w     = (const float*)d_in[14];
    const float* fc_b     = (const float*)d_in[15];
    const float* ln_g     = (const float*)d_in[18];
    const float* ln_b     = (const float*)d_in[19];
    const float* w_reg    = (const float*)d_in[22];
    const float* b_reg    = (const float*)d_in[23];
    const float* rm1      = (const float*)d_in[24];
    float* out = (float*)d_out;

    kInit<<<1, 1>>>();
    kA<<<(Nc + 127) / 128, 128>>>(node_emb, w1, b1, w2, b2, rm1, fc_w, fc_b);
    kV<<<(BNc + 127) / 128, 128>>>(x, w_input, b_input, fc_w);
    kB<<<dim3(PB, Bc), 256>>>();
    kB2<<<(Bc * Rc * H2c + Rc + 255) / 256, 256>>>();
    kC<<<(Nc + 127) / 128, 128>>>(ln_g, ln_b, w_reg, b_reg, out);
}

// round 6
// speedup vs baseline: 1.1083x; 1.0247x over previous
#include <cuda_runtime.h>
#include <math.h>

// ---------------- problem constants ----------------
#define Bc   4
#define Nc   50000
#define BNc  (Bc * Nc)
#define Tc   12
#define Hc   32
#define H2c  64
#define Rc   64

#define NRM     0.4204482076268573f   /* 32^-0.25 */
#define RATIO   0.125f                /* 64^-0.5  */
#define EPSP    1e-4f
#define EPS_LN  1e-5f

#define PB         391                /* kv partial blocks per batch */
#define CHUNK      128                /* nodes per kv block          */
#define TJ         32                 /* node tile in kv inner loop  */
#define NBLK       391                /* ceil(Nc/128)                */

// ---------------- f32x2 packed math (Blackwell) ----------------
__device__ __forceinline__ unsigned long long pk2(float a, float b) {
    unsigned long long r;
    asm("mov.b64 %0, {%1, %2};" : "=l"(r) : "f"(a), "f"(b));
    return r;
}
__device__ __forceinline__ void fma2(unsigned long long& d,
                                     unsigned long long a, unsigned long long b) {
    asm("fma.rn.f32x2 %0, %1, %2, %0;" : "+l"(d) : "l"(a), "l"(b));
}
__device__ __forceinline__ void upk2(float& lo, float& hi, unsigned long long v) {
    asm("mov.b64 {%0, %1}, %2;" : "=f"(lo), "=f"(hi) : "l"(v));
}

// ---------------- scratch ----------------
__device__ float    d_qp[Rc * Nc];
__device__ float    d_fk[Rc * Nc];
__device__ float    d_hnode[H2c * Nc];
__device__ float    d_neT[Hc * Nc];
__device__ float    d_h0[H2c * BNc];
__device__ float    d_ie[Hc * BNc];
__device__ unsigned d_keymax;
__device__ float    d_kv[Bc][Rc * H2c];
__device__ float    d_denv[Rc];
__device__ float    d_kvpart[Bc][PB][Rc * H2c];
__device__ float    d_denpart[Rc][PB];

__global__ void kInit() { d_keymax = 0u; }

__device__ __forceinline__ float decode_max(unsigned enc) {
    return (enc & 0x80000000u) ? __uint_as_float(enc ^ 0x80000000u)
                               : __uint_as_float(~enc);
}

// ---------------- Stage A: split y=0 queries (smem dd cache) | y=1 keys+hnode ----------------
__global__ void __launch_bounds__(128) kA(
    const float* __restrict__ node_emb,
    const float* __restrict__ w1, const float* __restrict__ b1,
    const float* __restrict__ w2, const float* __restrict__ b2,
    const float* __restrict__ rm1,
    const float* __restrict__ fc_w, const float* __restrict__ fc_b)
{
    __shared__ float sm[11424];
    int tid = threadIdx.x;
    int n = blockIdx.x * 128 + tid;

    if (blockIdx.y == 0) {
        // ---------- queries ----------
        float* s_w1 = sm;            // 1024
        float* s_rm = sm + 1024;     // 2048
        float* s_b1 = sm + 3072;     // 32
        float* s_dd = sm + 3104;     // 64*128 = 8192
        for (int i = tid; i < Hc * Hc; i += 128) s_w1[i] = w1[i];
        for (int i = tid; i < Rc * Hc; i += 128) s_rm[i] = rm1[i];
        if (tid < Hc) s_b1[tid] = b1[tid];
        __syncthreads();
        if (n >= Nc) return;

        float nd[Hc];
        #pragma unroll
        for (int d = 0; d < Hc; d++) nd[d] = node_emb[n * Hc + d];

        float nv[Hc];
        #pragma unroll
        for (int h = 0; h < Hc; h++) {
            float a = s_b1[h];
            #pragma unroll
            for (int d = 0; d < Hc; d++) a += nd[d] * s_w1[h * Hc + d];
            nv[h] = a;
        }
        float diag = 0.f;
        #pragma unroll
        for (int h = 0; h < Hc; h++) diag += nv[h] * nv[h];
        diag *= 0.5f * NRM * NRM;

        float mx = -3.0e38f;
        for (int r = 0; r < Rc; r++) {
            float a = 0.f;
            #pragma unroll
            for (int h = 0; h < Hc; h++) a += nv[h] * s_rm[r * Hc + h];
            a *= NRM;
            s_dd[r * 128 + tid] = a;
            mx = fmaxf(mx, a);
        }
        float base = diag + mx;
        for (int r = 0; r < Rc; r++)
            d_qp[r * Nc + n] = RATIO * (expf(s_dd[r * 128 + tid] - base) + EPSP);
    } else {
        // ---------- keys + hnode + neT ----------
        float* s_w2 = sm;            // 1024
        float* s_rm = sm + 1024;     // 2048
        float* s_fr = sm + 3072;     // 2048
        float* s_b2 = sm + 5120;     // 32
        float* s_fb = sm + 5152;     // 64
        for (int i = tid; i < Hc * Hc; i += 128) s_w2[i] = w2[i];
        for (int i = tid; i < Rc * Hc; i += 128) s_rm[i] = rm1[i];
        for (int i = tid; i < H2c * Hc; i += 128) {
            int o = i / Hc, d = i % Hc;
            s_fr[i] = fc_w[o * H2c + Hc + d];
        }
        if (tid < Hc)  s_b2[tid] = b2[tid];
        if (tid < H2c) s_fb[tid] = fc_b[tid];
        __syncthreads();

        float kmaxdd = -3.0e38f;
        if (n < Nc) {
            float nd[Hc];
            #pragma unroll
            for (int d = 0; d < Hc; d++) nd[d] = node_emb[n * Hc + d];
            #pragma unroll
            for (int d = 0; d < Hc; d++) d_neT[d * Nc + n] = nd[d];

            float nv[Hc];
            #pragma unroll
            for (int h = 0; h < Hc; h++) {
                float a = s_b2[h];
                #pragma unroll
                for (int d = 0; d < Hc; d++) a += nd[d] * s_w2[h * Hc + d];
                nv[h] = a;
            }
            float diagk = 0.f;
            #pragma unroll
            for (int h = 0; h < Hc; h++) diagk += nv[h] * nv[h];
            diagk *= 0.5f * NRM * NRM;

            for (int r = 0; r < Rc; r++) {
                float a = 0.f;
                #pragma unroll
                for (int h = 0; h < Hc; h++) a += nv[h] * s_rm[r * Hc + h];
                a *= NRM;
                d_fk[r * Nc + n] = a - diagk;
                kmaxdd = fmaxf(kmaxdd, a);
            }

            for (int o = 0; o < H2c; o++) {
                float a = s_fb[o];
                #pragma unroll
                for (int d = 0; d < Hc; d++) a += nd[d] * s_fr[o * Hc + d];
                d_hnode[o * Nc + n] = a;
            }
        }
        #pragma unroll
        for (int off = 16; off; off >>= 1)
            kmaxdd = fmaxf(kmaxdd, __shfl_xor_sync(0xffffffffu, kmaxdd, off));
        if ((tid & 31) == 0) {
            unsigned bits = __float_as_uint(kmaxdd);
            unsigned enc = (bits & 0x80000000u) ? ~bits : (bits | 0x80000000u);
            atomicMax(&d_keymax, enc);
        }
    }
}

// ---------------- Stage V: input_emb + v = relu(ie@fcwL + hnode), f32x2 ----------------
__global__ void __launch_bounds__(128) kV(
    const float* __restrict__ x,
    const float* __restrict__ w_input, const float* __restrict__ b_input,
    const float* __restrict__ fc_w)
{
    __shared__ float s_wi[Hc * Tc], s_bi[Hc], s_fl[H2c * Hc];
    int tid = threadIdx.x;
    for (int i = tid; i < Hc * Tc; i += 128) s_wi[i] = w_input[i];
    for (int i = tid; i < H2c * Hc; i += 128) {
        int o = i / Hc, d = i % Hc;
        s_fl[i] = fc_w[o * H2c + d];
    }
    if (tid < Hc) s_bi[tid] = b_input[tid];
    __syncthreads();

    int bn = blockIdx.x * 128 + tid;
    if (bn >= BNc) return;
    int n = bn % Nc;

    float xt[Tc];
    const float* xp = x + (size_t)bn * (Tc * 3);
    #pragma unroll
    for (int t = 0; t < Tc; t++) xt[t] = xp[t * 3];

    unsigned long long ie2[16];
    #pragma unroll
    for (int hp = 0; hp < 16; hp++) {
        int h0i = 2 * hp, h1i = 2 * hp + 1;
        float a0 = s_bi[h0i], a1 = s_bi[h1i];
        #pragma unroll
        for (int t = 0; t < Tc; t++) {
            a0 += xt[t] * s_wi[h0i * Tc + t];
            a1 += xt[t] * s_wi[h1i * Tc + t];
        }
        d_ie[(size_t)h0i * BNc + bn] = a0;
        d_ie[(size_t)h1i * BNc + bn] = a1;
        ie2[hp] = pk2(a0, a1);
    }

    for (int o = 0; o < H2c; o++) {
        unsigned long long acc_a = 0ull, acc_b = 0ull;
        const float4* fl4 = (const float4*)&s_fl[o * Hc];
        #pragma unroll
        for (int k = 0; k < 8; k++) {
            float4 f = fl4[k];
            fma2(acc_a, ie2[2 * k + 0], pk2(f.x, f.y));
            fma2(acc_b, ie2[2 * k + 1], pk2(f.z, f.w));
        }
        float l0, hi0, l1, hi1;
        upk2(l0, hi0, acc_a);
        upk2(l1, hi1, acc_b);
        float a = d_hnode[o * Nc + n] + ((l0 + hi0) + (l1 + hi1));
        d_h0[(size_t)o * BNc + bn] = fmaxf(a, 0.f);
    }
}

// ---------------- Stage B: kv partials + inline exp(kp) + den (b==0) ----------------
__global__ void __launch_bounds__(256) kB()
{
    int b = blockIdx.y, p = blockIdx.x;
    int n0 = p * CHUNK;
    int n1 = min(n0 + CHUNK, Nc);
    int tid = threadIdx.x;
    int r = tid & 63;
    int cg = tid >> 6;

    __shared__ float s_kp[TJ][Rc + 1];
    __shared__ float s_v[TJ][H2c + 4];

    float M = decode_max(d_keymax);

    unsigned long long acc2[8];
    #pragma unroll
    for (int q = 0; q < 8; q++) acc2[q] = 0ull;
    float dreg = 0.f;

    for (int jt = n0; jt < n1; jt += TJ) {
        int cnt = min(TJ, n1 - jt);
        for (int k = tid; k < Rc * TJ; k += 256) {
            int rr = k >> 5, j = k & 31;
            float v = 0.f;
            if (j < cnt)
                v = RATIO * (__expf(d_fk[rr * Nc + jt + j] - M) + EPSP);
            s_kp[j][rr] = v;
        }
        for (int k = tid; k < H2c * TJ; k += 256) {
            int c = k >> 5, j = k & 31;
            s_v[j][c] = (j < cnt) ? d_h0[(size_t)c * BNc + (size_t)b * Nc + jt + j] : 0.f;
        }
        __syncthreads();

        if (b == 0 && tid < 64) {
            #pragma unroll 8
            for (int j = 0; j < TJ; j++) dreg += s_kp[j][tid];
        }

        #pragma unroll 2
        for (int j = 0; j < TJ; j++) {
            float kpv = s_kp[j][r];
            unsigned long long q2 = pk2(kpv, kpv);
            const float4* vp = (const float4*)&s_v[j][cg * 16];
            #pragma unroll
            for (int q = 0; q < 4; q++) {
                float4 v4 = vp[q];
                fma2(acc2[q * 2 + 0], q2, pk2(v4.x, v4.y));
                fma2(acc2[q * 2 + 1], q2, pk2(v4.z, v4.w));
            }
        }
        __syncthreads();
    }

    float accf[16];
    #pragma unroll
    for (int q = 0; q < 8; q++) upk2(accf[q * 2], accf[q * 2 + 1], acc2[q]);
    float* dst = &d_kvpart[b][p][r * H2c + cg * 16];
    #pragma unroll
    for (int q = 0; q < 4; q++)
        ((float4*)dst)[q] = make_float4(accf[q * 4 + 0], accf[q * 4 + 1],
                                        accf[q * 4 + 2], accf[q * 4 + 3]);
    if (b == 0 && tid < 64) d_denpart[tid][p] = dreg;
}

// ---------------- reduce kv + den partials ----------------
__global__ void __launch_bounds__(256) kB2()
{
    int idx = blockIdx.x * 256 + threadIdx.x;
    if (idx < Bc * Rc * H2c) {
        int b = idx / (Rc * H2c), rc = idx % (Rc * H2c);
        float s = 0.f;
        for (int p = 0; p < PB; p++) s += d_kvpart[b][p][rc];
        d_kv[b][rc] = s;
    } else if (idx < Bc * Rc * H2c + Rc) {
        int r = idx - Bc * Rc * H2c;
        float s = 0.f;
        for (int p = 0; p < PB; p++) s += d_denpart[r][p];
        d_denv[r] = s;
    }
}

// ---------------- Stage C: 2D grid; streaming qp (f32x2), LN, out GEMM ----------------
__global__ void __launch_bounds__(128) kC(
    const float* __restrict__ ln_g, const float* __restrict__ ln_b,
    const float* __restrict__ w_reg, const float* __restrict__ b_reg,
    float* __restrict__ out)
{
    int b = blockIdx.y;
    __shared__ float4 s_kv4[Rc * 16];
    __shared__ float4 s_wr4[12 * 32];
    __shared__ float  s_den[Rc], s_g[H2c], s_be[H2c], s_br[12];
    int tid = threadIdx.x;
    {
        const float4* kvsrc = (const float4*)&d_kv[b][0];
        for (int i = tid; i < Rc * 16; i += 128) s_kv4[i] = kvsrc[i];
        const float4* wrsrc = (const float4*)w_reg;
        for (int i = tid; i < 12 * 32; i += 128) s_wr4[i] = wrsrc[i];
    }
    if (tid < Rc)  s_den[tid] = d_denv[tid];
    if (tid < H2c) { s_g[tid] = ln_g[tid]; s_be[tid] = ln_b[tid]; }
    if (tid < 12)  s_br[tid] = b_reg[tid];
    __syncthreads();

    int n = blockIdx.x * 128 + tid;
    if (n >= Nc) return;
    int bn = b * Nc + n;

    unsigned long long h2[32];
    #pragma unroll
    for (int c = 0; c < 32; c++) h2[c] = 0ull;
    float den = 0.f;

    #pragma unroll 4
    for (int r = 0; r < Rc; r++) {
        float q = d_qp[r * Nc + n];
        den += q * s_den[r];
        unsigned long long q2 = pk2(q, q);
        const float4* kvp = &s_kv4[r * 16];
        #pragma unroll
        for (int c4 = 0; c4 < 16; c4++) {
            float4 v = kvp[c4];
            fma2(h2[c4 * 2 + 0], q2, pk2(v.x, v.y));
            fma2(h2[c4 * 2 + 1], q2, pk2(v.z, v.w));
        }
    }

    float h[H2c];
    #pragma unroll
    for (int c = 0; c < 32; c++) upk2(h[c * 2], h[c * 2 + 1], h2[c]);

    float inv = 1.f / den;
    float outr[12];
    #pragma unroll
    for (int o = 0; o < 12; o++) outr[o] = s_br[o];

    float mu = 0.f;
    #pragma unroll
    for (int c4 = 0; c4 < 8; c4++) {
        float v0 = d_ie[(size_t)(c4 * 4 + 0) * BNc + bn];
        float v1 = d_ie[(size_t)(c4 * 4 + 1) * BNc + bn];
        float v2 = d_ie[(size_t)(c4 * 4 + 2) * BNc + bn];
        float v3 = d_ie[(size_t)(c4 * 4 + 3) * BNc + bn];
        h[c4 * 4 + 0] = h[c4 * 4 + 0] * inv + v0; mu += h[c4 * 4 + 0];
        h[c4 * 4 + 1] = h[c4 * 4 + 1] * inv + v1; mu += h[c4 * 4 + 1];
        h[c4 * 4 + 2] = h[c4 * 4 + 2] * inv + v2; mu += h[c4 * 4 + 2];
        h[c4 * 4 + 3] = h[c4 * 4 + 3] * inv + v3; mu += h[c4 * 4 + 3];
        float xv0 = fmaxf(v0, 0.f), xv1 = fmaxf(v1, 0.f);
        float xv2 = fmaxf(v2, 0.f), xv3 = fmaxf(v3, 0.f);
        #pragma unroll
        for (int o = 0; o < 12; o++) {
            float4 w = s_wr4[o * 32 + c4];
            outr[o] += xv0 * w.x + xv1 * w.y + xv2 * w.z + xv3 * w.w;
        }
    }
    #pragma unroll
    for (int c4 = 8; c4 < 16; c4++) {
        float v0 = d_neT[(c4 * 4 + 0 - Hc) * Nc + n];
        float v1 = d_neT[(c4 * 4 + 1 - Hc) * Nc + n];
        float v2 = d_neT[(c4 * 4 + 2 - Hc) * Nc + n];
        float v3 = d_neT[(c4 * 4 + 3 - Hc) * Nc + n];
        h[c4 * 4 + 0] = h[c4 * 4 + 0] * inv + v0; mu += h[c4 * 4 + 0];
        h[c4 * 4 + 1] = h[c4 * 4 + 1] * inv + v1; mu += h[c4 * 4 + 1];
        h[c4 * 4 + 2] = h[c4 * 4 + 2] * inv + v2; mu += h[c4 * 4 + 2];
        h[c4 * 4 + 3] = h[c4 * 4 + 3] * inv + v3; mu += h[c4 * 4 + 3];
        float xv0 = fmaxf(v0, 0.f), xv1 = fmaxf(v1, 0.f);
        float xv2 = fmaxf(v2, 0.f), xv3 = fmaxf(v3, 0.f);
        #pragma unroll
        for (int o = 0; o < 12; o++) {
            float4 w = s_wr4[o * 32 + c4];
            outr[o] += xv0 * w.x + xv1 * w.y + xv2 * w.z + xv3 * w.w;
        }
    }

    mu *= (1.f / H2c);
    float var = 0.f;
    #pragma unroll
    for (int c = 0; c < H2c; c++) { float d0 = h[c] - mu; var += d0 * d0; }
    var *= (1.f / H2c);
    float rstd = rsqrtf(var + EPS_LN);
    #pragma unroll
    for (int c = 0; c < H2c; c++)
        h[c] = fmaxf((h[c] - mu) * rstd * s_g[c] + s_be[c], 0.f);

    #pragma unroll
    for (int c4 = 0; c4 < 16; c4++) {
        float h0v = h[c4 * 4 + 0], h1v = h[c4 * 4 + 1];
        float h2v = h[c4 * 4 + 2], h3v = h[c4 * 4 + 3];
        #pragma unroll
        for (int o = 0; o < 12; o++) {
            float4 w = s_wr4[o * 32 + 16 + c4];
            outr[o] += h0v * w.x + h1v * w.y + h2v * w.z + h3v * w.w;
        }
    }

    float* op = out + (size_t)bn * 12;
    #pragma unroll
    for (int o = 0; o < 12; o++) op[o] = outr[o];
}

// ---------------- launch ----------------
extern "C" void kernel_launch(void* const* d_in, const int* in_sizes, int n_in,
                              void* d_out, int out_size)
{
    (void)in_sizes; (void)n_in; (void)out_size;
    const float* x        = (const float*)d_in[0];
    const float* node_emb = (const float*)d_in[1];
    const float* w_input  = (const float*)d_in[4];
    const float* b_input  = (const float*)d_in[5];
    const float* w1       = (const float*)d_in[6];
    const float* b1       = (const float*)d_in[7];
    const float* w2       = (const float*)d_in[8];
    const float* b2       = (const float*)d_in[9];
    const float* fc_w     = (const float*)d_in[14];
    const float* fc_b     = (const float*)d_in[15];
    const float* ln_g     = (const float*)d_in[18];
    const float* ln_b     = (const float*)d_in[19];
    const float* w_reg    = (const float*)d_in[22];
    const float* b_reg    = (const float*)d_in[23];
    const float* rm1      = (const float*)d_in[24];
    float* out = (float*)d_out;

    kInit<<<1, 1>>>();
    kA<<<dim3(NBLK, 2), 128>>>(node_emb, w1, b1, w2, b2, rm1, fc_w, fc_b);
    kV<<<(BNc + 127) / 128, 128>>>(x, w_input, b_input, fc_w);
    kB<<<dim3(PB, Bc), 256>>>();
    kB2<<<(Bc * Rc * H2c + Rc + 255) / 256, 256>>>();
    kC<<<dim3(NBLK, Bc), 128>>>(ln_g, ln_b, w_reg, b_reg, out);
}

// round 7
// speedup vs baseline: 1.1607x; 1.0472x over previous
#include <cuda_runtime.h>
#include <math.h>

// ---------------- problem constants ----------------
#define Bc   4
#define Nc   50000
#define BNc  (Bc * Nc)
#define Tc   12
#define Hc   32
#define H2c  64
#define Rc   64

#define NRM     0.4204482076268573f   /* 32^-0.25 */
#define RATIO   0.125f                /* 64^-0.5  */
#define EPSP    1e-4f
#define EPS_LN  1e-5f

#define PB         391                /* kv partial blocks per batch */
#define CHUNK      128                /* nodes per kv block          */
#define TJ         32                 /* k tile in kv inner loop     */
#define NBLK       391                /* ceil(Nc/128)                */

typedef unsigned long long u64;

// ---------------- f32x2 packed math (Blackwell) ----------------
__device__ __forceinline__ u64 pk2(float a, float b) {
    u64 r;
    asm("mov.b64 %0, {%1, %2};" : "=l"(r) : "f"(a), "f"(b));
    return r;
}
__device__ __forceinline__ void fma2(u64& d, u64 a, u64 b) {
    asm("fma.rn.f32x2 %0, %1, %2, %0;" : "+l"(d) : "l"(a), "l"(b));
}
__device__ __forceinline__ void upk2(float& lo, float& hi, u64 v) {
    asm("mov.b64 {%0, %1}, %2;" : "=f"(lo), "=f"(hi) : "l"(v));
}

// ---------------- scratch ----------------
__device__ float    d_qp[Rc * Nc];
__device__ float    d_fk[Rc * Nc];
__device__ float    d_hnode[H2c * Nc];
__device__ float    d_neT[Hc * Nc];
__device__ float    d_h0[H2c * BNc];
__device__ float    d_ie[Hc * BNc];
__device__ unsigned d_keymax;
__device__ float    d_kv[Bc][Rc * H2c];
__device__ float    d_denv[Rc];
__device__ float    d_kvpart[Bc][PB][Rc * H2c];
__device__ float    d_denpart[Rc][PB];

__global__ void kInit() { d_keymax = 0u; }

__device__ __forceinline__ float decode_max(unsigned enc) {
    return (enc & 0x80000000u) ? __uint_as_float(enc ^ 0x80000000u)
                               : __uint_as_float(~enc);
}

// ---------------- Stage A: split y=0 queries (smem dd cache) | y=1 keys+hnode ----------------
__global__ void __launch_bounds__(128) kA(
    const float* __restrict__ node_emb,
    const float* __restrict__ w1, const float* __restrict__ b1,
    const float* __restrict__ w2, const float* __restrict__ b2,
    const float* __restrict__ rm1,
    const float* __restrict__ fc_w, const float* __restrict__ fc_b)
{
    __shared__ float sm[11424];
    int tid = threadIdx.x;
    int n = blockIdx.x * 128 + tid;

    if (blockIdx.y == 0) {
        // ---------- queries ----------
        float* s_w1 = sm;            // 1024
        float* s_rm = sm + 1024;     // 2048
        float* s_b1 = sm + 3072;     // 32
        float* s_dd = sm + 3104;     // 64*128 = 8192
        for (int i = tid; i < Hc * Hc; i += 128) s_w1[i] = w1[i];
        for (int i = tid; i < Rc * Hc; i += 128) s_rm[i] = rm1[i];
        if (tid < Hc) s_b1[tid] = b1[tid];
        __syncthreads();
        if (n >= Nc) return;

        float nd[Hc];
        #pragma unroll
        for (int d = 0; d < Hc; d++) nd[d] = node_emb[n * Hc + d];

        float nv[Hc];
        #pragma unroll
        for (int h = 0; h < Hc; h++) {
            float a = s_b1[h];
            #pragma unroll
            for (int d = 0; d < Hc; d++) a += nd[d] * s_w1[h * Hc + d];
            nv[h] = a;
        }
        float diag = 0.f;
        #pragma unroll
        for (int h = 0; h < Hc; h++) diag += nv[h] * nv[h];
        diag *= 0.5f * NRM * NRM;

        float mx = -3.0e38f;
        for (int r = 0; r < Rc; r++) {
            float a = 0.f;
            #pragma unroll
            for (int h = 0; h < Hc; h++) a += nv[h] * s_rm[r * Hc + h];
            a *= NRM;
            s_dd[r * 128 + tid] = a;
            mx = fmaxf(mx, a);
        }
        float base = diag + mx;
        for (int r = 0; r < Rc; r++)
            d_qp[r * Nc + n] = RATIO * (__expf(s_dd[r * 128 + tid] - base) + EPSP);
    } else {
        // ---------- keys + hnode + neT ----------
        float* s_w2 = sm;            // 1024
        float* s_rm = sm + 1024;     // 2048
        float* s_fr = sm + 3072;     // 2048
        float* s_b2 = sm + 5120;     // 32
        float* s_fb = sm + 5152;     // 64
        for (int i = tid; i < Hc * Hc; i += 128) s_w2[i] = w2[i];
        for (int i = tid; i < Rc * Hc; i += 128) s_rm[i] = rm1[i];
        for (int i = tid; i < H2c * Hc; i += 128) {
            int o = i / Hc, d = i % Hc;
            s_fr[i] = fc_w[o * H2c + Hc + d];
        }
        if (tid < Hc)  s_b2[tid] = b2[tid];
        if (tid < H2c) s_fb[tid] = fc_b[tid];
        __syncthreads();

        float kmaxdd = -3.0e38f;
        if (n < Nc) {
            float nd[Hc];
            #pragma unroll
            for (int d = 0; d < Hc; d++) nd[d] = node_emb[n * Hc + d];
            #pragma unroll
            for (int d = 0; d < Hc; d++) d_neT[d * Nc + n] = nd[d];

            float nv[Hc];
            #pragma unroll
            for (int h = 0; h < Hc; h++) {
                float a = s_b2[h];
                #pragma unroll
                for (int d = 0; d < Hc; d++) a += nd[d] * s_w2[h * Hc + d];
                nv[h] = a;
            }
            float diagk = 0.f;
            #pragma unroll
            for (int h = 0; h < Hc; h++) diagk += nv[h] * nv[h];
            diagk *= 0.5f * NRM * NRM;

            for (int r = 0; r < Rc; r++) {
                float a = 0.f;
                #pragma unroll
                for (int h = 0; h < Hc; h++) a += nv[h] * s_rm[r * Hc + h];
                a *= NRM;
                d_fk[r * Nc + n] = a - diagk;
                kmaxdd = fmaxf(kmaxdd, a);
            }

            for (int o = 0; o < H2c; o++) {
                float a = s_fb[o];
                #pragma unroll
                for (int d = 0; d < Hc; d++) a += nd[d] * s_fr[o * Hc + d];
                d_hnode[o * Nc + n] = a;
            }
        }
        #pragma unroll
        for (int off = 16; off; off >>= 1)
            kmaxdd = fmaxf(kmaxdd, __shfl_xor_sync(0xffffffffu, kmaxdd, off));
        if ((tid & 31) == 0) {
            unsigned bits = __float_as_uint(kmaxdd);
            unsigned enc = (bits & 0x80000000u) ? ~bits : (bits | 0x80000000u);
            atomicMax(&d_keymax, enc);
        }
    }
}

// ---------------- Stage V: input_emb + v = relu(ie@fcwL + hnode), packed loads ----------------
__global__ void __launch_bounds__(128) kV(
    const float* __restrict__ x,
    const float* __restrict__ w_input, const float* __restrict__ b_input,
    const float* __restrict__ fc_w)
{
    __shared__ float s_wi[Hc * Tc], s_bi[Hc], s_fl[H2c * Hc];
    int tid = threadIdx.x;
    for (int i = tid; i < Hc * Tc; i += 128) s_wi[i] = w_input[i];
    for (int i = tid; i < H2c * Hc; i += 128) {
        int o = i / Hc, d = i % Hc;
        s_fl[i] = fc_w[o * H2c + d];
    }
    if (tid < Hc) s_bi[tid] = b_input[tid];
    __syncthreads();

    int bn = blockIdx.x * 128 + tid;
    if (bn >= BNc) return;
    int n = bn % Nc;

    float xt[Tc];
    const float* xp = x + (size_t)bn * (Tc * 3);
    #pragma unroll
    for (int t = 0; t < Tc; t++) xt[t] = xp[t * 3];

    u64 ie2[16];
    #pragma unroll
    for (int hp = 0; hp < 16; hp++) {
        int h0i = 2 * hp, h1i = 2 * hp + 1;
        float a0 = s_bi[h0i], a1 = s_bi[h1i];
        #pragma unroll
        for (int t = 0; t < Tc; t++) {
            a0 += xt[t] * s_wi[h0i * Tc + t];
            a1 += xt[t] * s_wi[h1i * Tc + t];
        }
        d_ie[(size_t)h0i * BNc + bn] = a0;
        d_ie[(size_t)h1i * BNc + bn] = a1;
        ie2[hp] = pk2(a0, a1);
    }

    for (int o = 0; o < H2c; o++) {
        u64 acc_a = 0ull, acc_b = 0ull;
        const ulonglong2* fl2 = (const ulonglong2*)&s_fl[o * Hc];
        #pragma unroll
        for (int k = 0; k < 8; k++) {
            ulonglong2 f = fl2[k];
            fma2(acc_a, ie2[2 * k + 0], f.x);
            fma2(acc_b, ie2[2 * k + 1], f.y);
        }
        float l0, hi0, l1, hi1;
        upk2(l0, hi0, acc_a);
        upk2(l1, hi1, acc_b);
        float a = d_hnode[o * Nc + n] + ((l0 + hi0) + (l1 + hi1));
        d_h0[(size_t)o * BNc + bn] = fmaxf(a, 0.f);
    }
}

// ---------------- Stage B: outer-product kv partials + inline exp + den (b==0) ----------------
__global__ void __launch_bounds__(256) kB()
{
    int b = blockIdx.y, p = blockIdx.x;
    int n0 = p * CHUNK;
    int n1 = min(n0 + CHUNK, Nc);
    int tid = threadIdx.x;
    int ty = tid >> 4;                  // 0..15: r-group (4 rows)
    int tx = tid & 15;                  // 0..15: c-group (4 cols)

    __shared__ float s_a[TJ][68];       // [k][r]  kp
    __shared__ float s_v[TJ][68];       // [k][c]  h0

    float M = decode_max(d_keymax);

    u64 acc2[4][2];
    #pragma unroll
    for (int i = 0; i < 4; i++) { acc2[i][0] = 0ull; acc2[i][1] = 0ull; }
    float dreg = 0.f;

    for (int jt = n0; jt < n1; jt += TJ) {
        int cnt = min(TJ, n1 - jt);
        // stage kp[k][r] (coalesced over k)
        for (int idx = tid; idx < Rc * TJ; idx += 256) {
            int rr = idx >> 5, kk = idx & 31;
            float v = 0.f;
            if (kk < cnt)
                v = RATIO * (__expf(d_fk[rr * Nc + jt + kk] - M) + EPSP);
            s_a[kk][rr] = v;
        }
        // stage h0[k][c] (coalesced over k)
        for (int idx = tid; idx < H2c * TJ; idx += 256) {
            int cc = idx >> 5, kk = idx & 31;
            s_v[kk][cc] = (kk < cnt)
                ? d_h0[(size_t)cc * BNc + (size_t)b * Nc + jt + kk] : 0.f;
        }
        __syncthreads();

        if (b == 0 && tid < 64) {
            #pragma unroll 8
            for (int k = 0; k < TJ; k++) dreg += s_a[k][tid];
        }

        #pragma unroll 4
        for (int k = 0; k < TJ; k++) {
            float4 af = *(const float4*)&s_a[k][ty * 4];
            ulonglong2 bv = *(const ulonglong2*)&s_v[k][tx * 4];
            u64 a0 = pk2(af.x, af.x);
            u64 a1 = pk2(af.y, af.y);
            u64 a2 = pk2(af.z, af.z);
            u64 a3 = pk2(af.w, af.w);
            fma2(acc2[0][0], a0, bv.x); fma2(acc2[0][1], a0, bv.y);
            fma2(acc2[1][0], a1, bv.x); fma2(acc2[1][1], a1, bv.y);
            fma2(acc2[2][0], a2, bv.x); fma2(acc2[2][1], a2, bv.y);
            fma2(acc2[3][0], a3, bv.x); fma2(acc2[3][1], a3, bv.y);
        }
        __syncthreads();
    }

    #pragma unroll
    for (int i = 0; i < 4; i++) {
        float f0, f1, f2, f3;
        upk2(f0, f1, acc2[i][0]);
        upk2(f2, f3, acc2[i][1]);
        *(float4*)&d_kvpart[b][p][(ty * 4 + i) * H2c + tx * 4] =
            make_float4(f0, f1, f2, f3);
    }
    if (b == 0 && tid < 64) d_denpart[tid][p] = dreg;
}

// ---------------- reduce kv + den partials ----------------
__global__ void __launch_bounds__(256) kB2()
{
    int idx = blockIdx.x * 256 + threadIdx.x;
    if (idx < Bc * Rc * H2c) {
        int b = idx / (Rc * H2c), rc = idx % (Rc * H2c);
        float s = 0.f;
        for (int p = 0; p < PB; p++) s += d_kvpart[b][p][rc];
        d_kv[b][rc] = s;
    } else if (idx < Bc * Rc * H2c + Rc) {
        int r = idx - Bc * Rc * H2c;
        float s = 0.f;
        for (int p = 0; p < PB; p++) s += d_denpart[r][p];
        d_denv[r] = s;
    }
}

// ---------------- Stage C: packed-pair numerator + packed out GEMM ----------------
__global__ void __launch_bounds__(128) kC(
    const float* __restrict__ ln_g, const float* __restrict__ ln_b,
    const float* __restrict__ w_reg, const float* __restrict__ b_reg,
    float* __restrict__ out)
{
    int b = blockIdx.y;
    __shared__ u64  s_kv2[Rc * 32];            // kv as f32 pairs
    __shared__ u64  s_wr2[12 * 64];            // w_reg as f32 pairs
    __shared__ float s_den[Rc], s_g[H2c], s_be[H2c], s_br[12];
    int tid = threadIdx.x;
    {
        const ulonglong2* kvsrc = (const ulonglong2*)&d_kv[b][0];
        ulonglong2* kvdst = (ulonglong2*)s_kv2;
        for (int i = tid; i < Rc * 16; i += 128) kvdst[i] = kvsrc[i];
        const ulonglong2* wrsrc = (const ulonglong2*)w_reg;
        ulonglong2* wrdst = (ulonglong2*)s_wr2;
        for (int i = tid; i < 12 * 32; i += 128) wrdst[i] = wrsrc[i];
    }
    if (tid < Rc)  s_den[tid] = d_denv[tid];
    if (tid < H2c) { s_g[tid] = ln_g[tid]; s_be[tid] = ln_b[tid]; }
    if (tid < 12)  s_br[tid] = b_reg[tid];
    __syncthreads();

    int n = blockIdx.x * 128 + tid;
    if (n >= Nc) return;
    int bn = b * Nc + n;

    u64 h2[32];
    #pragma unroll
    for (int c = 0; c < 32; c++) h2[c] = 0ull;
    float den = 0.f;

    #pragma unroll 4
    for (int r = 0; r < Rc; r++) {
        float q = d_qp[r * Nc + n];
        den += q * s_den[r];
        u64 q2 = pk2(q, q);
        const ulonglong2* kvp = (const ulonglong2*)&s_kv2[r * 32];
        #pragma unroll
        for (int c8 = 0; c8 < 16; c8++) {
            ulonglong2 v = kvp[c8];
            fma2(h2[c8 * 2 + 0], q2, v.x);
            fma2(h2[c8 * 2 + 1], q2, v.y);
        }
    }

    float h[H2c];
    #pragma unroll
    for (int c = 0; c < 32; c++) upk2(h[c * 2], h[c * 2 + 1], h2[c]);

    float inv = 1.f / den;
    u64 oacc[12];
    #pragma unroll
    for (int o = 0; o < 12; o++) oacc[o] = 0ull;

    float mu = 0.f;
    // ie part (c = 0..31)
    #pragma unroll
    for (int c4 = 0; c4 < 8; c4++) {
        float v0 = d_ie[(size_t)(c4 * 4 + 0) * BNc + bn];
        float v1 = d_ie[(size_t)(c4 * 4 + 1) * BNc + bn];
        float v2 = d_ie[(size_t)(c4 * 4 + 2) * BNc + bn];
        float v3 = d_ie[(size_t)(c4 * 4 + 3) * BNc + bn];
        h[c4 * 4 + 0] = h[c4 * 4 + 0] * inv + v0; mu += h[c4 * 4 + 0];
        h[c4 * 4 + 1] = h[c4 * 4 + 1] * inv + v1; mu += h[c4 * 4 + 1];
        h[c4 * 4 + 2] = h[c4 * 4 + 2] * inv + v2; mu += h[c4 * 4 + 2];
        h[c4 * 4 + 3] = h[c4 * 4 + 3] * inv + v3; mu += h[c4 * 4 + 3];
        u64 xp01 = pk2(fmaxf(v0, 0.f), fmaxf(v1, 0.f));
        u64 xp23 = pk2(fmaxf(v2, 0.f), fmaxf(v3, 0.f));
        #pragma unroll
        for (int o = 0; o < 12; o++) {
            ulonglong2 w = *(const ulonglong2*)&s_wr2[o * 64 + c4 * 2];
            fma2(oacc[o], xp01, w.x);
            fma2(oacc[o], xp23, w.y);
        }
    }
    // node part (c = 32..63)
    #pragma unroll
    for (int c4 = 8; c4 < 16; c4++) {
        float v0 = d_neT[(c4 * 4 + 0 - Hc) * Nc + n];
        float v1 = d_neT[(c4 * 4 + 1 - Hc) * Nc + n];
        float v2 = d_neT[(c4 * 4 + 2 - Hc) * Nc + n];
        float v3 = d_neT[(c4 * 4 + 3 - Hc) * Nc + n];
        h[c4 * 4 + 0] = h[c4 * 4 + 0] * inv + v0; mu += h[c4 * 4 + 0];
        h[c4 * 4 + 1] = h[c4 * 4 + 1] * inv + v1; mu += h[c4 * 4 + 1];
        h[c4 * 4 + 2] = h[c4 * 4 + 2] * inv + v2; mu += h[c4 * 4 + 2];
        h[c4 * 4 + 3] = h[c4 * 4 + 3] * inv + v3; mu += h[c4 * 4 + 3];
        u64 xp01 = pk2(fmaxf(v0, 0.f), fmaxf(v1, 0.f));
        u64 xp23 = pk2(fmaxf(v2, 0.f), fmaxf(v3, 0.f));
        #pragma unroll
        for (int o = 0; o < 12; o++) {
            ulonglong2 w = *(const ulonglong2*)&s_wr2[o * 64 + c4 * 2];
            fma2(oacc[o], xp01, w.x);
            fma2(oacc[o], xp23, w.y);
        }
    }

    mu *= (1.f / H2c);
    float var = 0.f;
    #pragma unroll
    for (int c = 0; c < H2c; c++) { float d0 = h[c] - mu; var += d0 * d0; }
    var *= (1.f / H2c);
    float rstd = rsqrtf(var + EPS_LN);
    #pragma unroll
    for (int c = 0; c < H2c; c++)
        h[c] = fmaxf((h[c] - mu) * rstd * s_g[c] + s_be[c], 0.f);

    #pragma unroll
    for (int c4 = 0; c4 < 16; c4++) {
        u64 hp01 = pk2(h[c4 * 4 + 0], h[c4 * 4 + 1]);
        u64 hp23 = pk2(h[c4 * 4 + 2], h[c4 * 4 + 3]);
        #pragma unroll
        for (int o = 0; o < 12; o++) {
            ulonglong2 w = *(const ulonglong2*)&s_wr2[o * 64 + 32 + c4 * 2];
            fma2(oacc[o], hp01, w.x);
            fma2(oacc[o], hp23, w.y);
        }
    }

    float* op = out + (size_t)bn * 12;
    #pragma unroll
    for (int o = 0; o < 12; o++) {
        float lo, hi;
        upk2(lo, hi, oacc[o]);
        op[o] = s_br[o] + lo + hi;
    }
}

// ---------------- launch ----------------
extern "C" void kernel_launch(void* const* d_in, const int* in_sizes, int n_in,
                              void* d_out, int out_size)
{
    (void)in_sizes; (void)n_in; (void)out_size;
    const float* x        = (const float*)d_in[0];
    const float* node_emb = (const float*)d_in[1];
    const float* w_input  = (const float*)d_in[4];
    const float* b_input  = (const float*)d_in[5];
    const float* w1       = (const float*)d_in[6];
    const float* b1       = (const float*)d_in[7];
    const float* w2       = (const float*)d_in[8];
    const float* b2       = (const float*)d_in[9];
    const float* fc_w     = (const float*)d_in[14];
    const float* fc_b     = (const float*)d_in[15];
    const float* ln_g     = (const float*)d_in[18];
    const float* ln_b     = (const float*)d_in[19];
    const float* w_reg    = (const float*)d_in[22];
    const float* b_reg    = (const float*)d_in[23];
    const float* rm1      = (const float*)d_in[24];
    float* out = (float*)d_out;

    kInit<<<1, 1>>>();
    kA<<<dim3(NBLK, 2), 128>>>(node_emb, w1, b1, w2, b2, rm1, fc_w, fc_b);
    kV<<<(BNc + 127) / 128, 128>>>(x, w_input, b_input, fc_w);
    kB<<<dim3(PB, Bc), 256>>>();
    kB2<<<(Bc * Rc * H2c + Rc + 255) / 256, 256>>>();
    kC<<<dim3(NBLK, Bc), 128>>>(ln_g, ln_b, w_reg, b_reg, out);
}

// round 8
// speedup vs baseline: 1.1634x; 1.0023x over previous
#include <cuda_runtime.h>
#include <math.h>

// ---------------- problem constants ----------------
#define Bc   4
#define Nc   50000
#define BNc  (Bc * Nc)
#define Tc   12
#define Hc   32
#define H2c  64
#define Rc   64

#define NRM     0.4204482076268573f   /* 32^-0.25 */
#define RATIO   0.125f                /* 64^-0.5  */
#define EPSP    1e-4f
#define EPS_LN  1e-5f

#define PB         391                /* kv partial blocks per batch */
#define CHUNK      128                /* nodes per kv block          */
#define TJ         32                 /* k tile in kv inner loop     */
#define NBLK       391                /* ceil(Nc/128)                */
#define DEN_CHUNKS 196                /* ceil(Nc/256)                */

typedef unsigned long long u64;

// ---------------- f32x2 packed math (Blackwell) ----------------
__device__ __forceinline__ u64 pk2(float a, float b) {
    u64 r;
    asm("mov.b64 %0, {%1, %2};" : "=l"(r) : "f"(a), "f"(b));
    return r;
}
__device__ __forceinline__ void fma2(u64& d, u64 a, u64 b) {
    asm("fma.rn.f32x2 %0, %1, %2, %0;" : "+l"(d) : "l"(a), "l"(b));
}
__device__ __forceinline__ void upk2(float& lo, float& hi, u64 v) {
    asm("mov.b64 {%0, %1}, %2;" : "=f"(lo), "=f"(hi) : "l"(v));
}

// ---------------- scratch ----------------
__device__ float    d_qp[Rc * Nc];
__device__ float    d_fk[Rc * Nc];
__device__ float    d_kp[Rc * Nc];
__device__ float    d_hnode[H2c * Nc];
__device__ float    d_neT[Hc * Nc];
__device__ float    d_h0[H2c * BNc];
__device__ float    d_ie[Hc * BNc];
__device__ unsigned d_keymax;
__device__ float    d_kv[Bc][Rc * H2c];
__device__ float    d_denv[Rc];
__device__ float    d_kvpart[Bc][PB][Rc * H2c];
__device__ float    d_denpart[Rc][DEN_CHUNKS];

__global__ void kInit() { d_keymax = 0u; }

__device__ __forceinline__ float decode_max(unsigned enc) {
    return (enc & 0x80000000u) ? __uint_as_float(enc ^ 0x80000000u)
                               : __uint_as_float(~enc);
}

// ---------------- Stage A: split y=0 queries (smem dd cache) | y=1 keys+hnode ----------------
__global__ void __launch_bounds__(128) kA(
    const float* __restrict__ node_emb,
    const float* __restrict__ w1, const float* __restrict__ b1,
    const float* __restrict__ w2, const float* __restrict__ b2,
    const float* __restrict__ rm1,
    const float* __restrict__ fc_w, const float* __restrict__ fc_b)
{
    __shared__ float sm[11424];
    int tid = threadIdx.x;
    int n = blockIdx.x * 128 + tid;

    if (blockIdx.y == 0) {
        // ---------- queries ----------
        float* s_w1 = sm;            // 1024
        float* s_rm = sm + 1024;     // 2048
        float* s_b1 = sm + 3072;     // 32
        float* s_dd = sm + 3104;     // 64*128 = 8192
        for (int i = tid; i < Hc * Hc; i += 128) s_w1[i] = w1[i];
        for (int i = tid; i < Rc * Hc; i += 128) s_rm[i] = rm1[i];
        if (tid < Hc) s_b1[tid] = b1[tid];
        __syncthreads();
        if (n >= Nc) return;

        float nd[Hc];
        #pragma unroll
        for (int d = 0; d < Hc; d++) nd[d] = node_emb[n * Hc + d];

        float nv[Hc];
        #pragma unroll
        for (int h = 0; h < Hc; h++) {
            float a = s_b1[h];
            #pragma unroll
            for (int d = 0; d < Hc; d++) a += nd[d] * s_w1[h * Hc + d];
            nv[h] = a;
        }
        float diag = 0.f;
        #pragma unroll
        for (int h = 0; h < Hc; h++) diag += nv[h] * nv[h];
        diag *= 0.5f * NRM * NRM;

        float mx = -3.0e38f;
        for (int r = 0; r < Rc; r++) {
            float a = 0.f;
            #pragma unroll
            for (int h = 0; h < Hc; h++) a += nv[h] * s_rm[r * Hc + h];
            a *= NRM;
            s_dd[r * 128 + tid] = a;
            mx = fmaxf(mx, a);
        }
        float base = diag + mx;
        for (int r = 0; r < Rc; r++)
            d_qp[r * Nc + n] = RATIO * (__expf(s_dd[r * 128 + tid] - base) + EPSP);
    } else {
        // ---------- keys + hnode + neT ----------
        float* s_w2 = sm;            // 1024
        float* s_rm = sm + 1024;     // 2048
        float* s_fr = sm + 3072;     // 2048
        float* s_b2 = sm + 5120;     // 32
        float* s_fb = sm + 5152;     // 64
        for (int i = tid; i < Hc * Hc; i += 128) s_w2[i] = w2[i];
        for (int i = tid; i < Rc * Hc; i += 128) s_rm[i] = rm1[i];
        for (int i = tid; i < H2c * Hc; i += 128) {
            int o = i / Hc, d = i % Hc;
            s_fr[i] = fc_w[o * H2c + Hc + d];
        }
        if (tid < Hc)  s_b2[tid] = b2[tid];
        if (tid < H2c) s_fb[tid] = fc_b[tid];
        __syncthreads();

        float kmaxdd = -3.0e38f;
        if (n < Nc) {
            float nd[Hc];
            #pragma unroll
            for (int d = 0; d < Hc; d++) nd[d] = node_emb[n * Hc + d];
            #pragma unroll
            for (int d = 0; d < Hc; d++) d_neT[d * Nc + n] = nd[d];

            float nv[Hc];
            #pragma unroll
            for (int h = 0; h < Hc; h++) {
                float a = s_b2[h];
                #pragma unroll
                for (int d = 0; d < Hc; d++) a += nd[d] * s_w2[h * Hc + d];
                nv[h] = a;
            }
            float diagk = 0.f;
            #pragma unroll
            for (int h = 0; h < Hc; h++) diagk += nv[h] * nv[h];
            diagk *= 0.5f * NRM * NRM;

            for (int r = 0; r < Rc; r++) {
                float a = 0.f;
                #pragma unroll
                for (int h = 0; h < Hc; h++) a += nv[h] * s_rm[r * Hc + h];
                a *= NRM;
                d_fk[r * Nc + n] = a - diagk;
                kmaxdd = fmaxf(kmaxdd, a);
            }

            for (int o = 0; o < H2c; o++) {
                float a = s_fb[o];
                #pragma unroll
                for (int d = 0; d < Hc; d++) a += nd[d] * s_fr[o * Hc + d];
                d_hnode[o * Nc + n] = a;
            }
        }
        #pragma unroll
        for (int off = 16; off; off >>= 1)
            kmaxdd = fmaxf(kmaxdd, __shfl_xor_sync(0xffffffffu, kmaxdd, off));
        if ((tid & 31) == 0) {
            unsigned bits = __float_as_uint(kmaxdd);
            unsigned enc = (bits & 0x80000000u) ? ~bits : (bits | 0x80000000u);
            atomicMax(&d_keymax, enc);
        }
    }
}

// ---------------- kKP: kp = ratio*(exp(fk - M) + eps) once; den partials ----------------
__global__ void __launch_bounds__(256) kKP()
{
    int r = blockIdx.y;
    int n = blockIdx.x * 256 + threadIdx.x;
    float M = decode_max(d_keymax);
    float v = 0.f;
    if (n < Nc) {
        v = RATIO * (__expf(d_fk[r * Nc + n] - M) + EPSP);
        d_kp[r * Nc + n] = v;
    }
    // block reduction for den
    #pragma unroll
    for (int off = 16; off; off >>= 1)
        v += __shfl_xor_sync(0xffffffffu, v, off);
    __shared__ float red[8];
    if ((threadIdx.x & 31) == 0) red[threadIdx.x >> 5] = v;
    __syncthreads();
    if (threadIdx.x < 8) {
        float s = red[threadIdx.x];
        #pragma unroll
        for (int off = 4; off; off >>= 1)
            s += __shfl_xor_sync(0xffu, s, off);
        if (threadIdx.x == 0) d_denpart[r][blockIdx.x] = s;
    }
}

// ---------------- Stage V: input_emb + v = relu(ie@fcwL + hnode), packed loads ----------------
__global__ void __launch_bounds__(128) kV(
    const float* __restrict__ x,
    const float* __restrict__ w_input, const float* __restrict__ b_input,
    const float* __restrict__ fc_w)
{
    __shared__ float s_wi[Hc * Tc], s_bi[Hc], s_fl[H2c * Hc];
    int tid = threadIdx.x;
    for (int i = tid; i < Hc * Tc; i += 128) s_wi[i] = w_input[i];
    for (int i = tid; i < H2c * Hc; i += 128) {
        int o = i / Hc, d = i % Hc;
        s_fl[i] = fc_w[o * H2c + d];
    }
    if (tid < Hc) s_bi[tid] = b_input[tid];
    __syncthreads();

    int bn = blockIdx.x * 128 + tid;
    if (bn >= BNc) return;
    int n = bn % Nc;

    float xt[Tc];
    const float* xp = x + (size_t)bn * (Tc * 3);
    #pragma unroll
    for (int t = 0; t < Tc; t++) xt[t] = xp[t * 3];

    u64 ie2[16];
    #pragma unroll
    for (int hp = 0; hp < 16; hp++) {
        int h0i = 2 * hp, h1i = 2 * hp + 1;
        float a0 = s_bi[h0i], a1 = s_bi[h1i];
        #pragma unroll
        for (int t = 0; t < Tc; t++) {
            a0 += xt[t] * s_wi[h0i * Tc + t];
            a1 += xt[t] * s_wi[h1i * Tc + t];
        }
        d_ie[(size_t)h0i * BNc + bn] = a0;
        d_ie[(size_t)h1i * BNc + bn] = a1;
        ie2[hp] = pk2(a0, a1);
    }

    for (int o = 0; o < H2c; o++) {
        u64 acc_a = 0ull, acc_b = 0ull;
        const ulonglong2* fl2 = (const ulonglong2*)&s_fl[o * Hc];
        #pragma unroll
        for (int k = 0; k < 8; k++) {
            ulonglong2 f = fl2[k];
            fma2(acc_a, ie2[2 * k + 0], f.x);
            fma2(acc_b, ie2[2 * k + 1], f.y);
        }
        float l0, hi0, l1, hi1;
        upk2(l0, hi0, acc_a);
        upk2(l1, hi1, acc_b);
        float a = d_hnode[o * Nc + n] + ((l0 + hi0) + (l1 + hi1));
        d_h0[(size_t)o * BNc + bn] = fmaxf(a, 0.f);
    }
}

// ---------------- Stage B: outer-product kv partials (pure GEMM now) ----------------
__global__ void __launch_bounds__(256) kB()
{
    int b = blockIdx.y, p = blockIdx.x;
    int n0 = p * CHUNK;
    int n1 = min(n0 + CHUNK, Nc);
    int tid = threadIdx.x;
    int ty = tid >> 4;                  // 0..15: r-group (4 rows)
    int tx = tid & 15;                  // 0..15: c-group (4 cols)

    __shared__ float s_a[TJ][68];       // [k][r]  kp
    __shared__ float s_v[TJ][68];       // [k][c]  h0

    u64 acc2[4][2];
    #pragma unroll
    for (int i = 0; i < 4; i++) { acc2[i][0] = 0ull; acc2[i][1] = 0ull; }

    for (int jt = n0; jt < n1; jt += TJ) {
        int cnt = min(TJ, n1 - jt);
        for (int idx = tid; idx < Rc * TJ; idx += 256) {
            int rr = idx >> 5, kk = idx & 31;
            s_a[kk][rr] = (kk < cnt) ? d_kp[rr * Nc + jt + kk] : 0.f;
        }
        for (int idx = tid; idx < H2c * TJ; idx += 256) {
            int cc = idx >> 5, kk = idx & 31;
            s_v[kk][cc] = (kk < cnt)
                ? d_h0[(size_t)cc * BNc + (size_t)b * Nc + jt + kk] : 0.f;
        }
        __syncthreads();

        #pragma unroll 4
        for (int k = 0; k < TJ; k++) {
            float4 af = *(const float4*)&s_a[k][ty * 4];
            ulonglong2 bv = *(const ulonglong2*)&s_v[k][tx * 4];
            u64 a0 = pk2(af.x, af.x);
            u64 a1 = pk2(af.y, af.y);
            u64 a2 = pk2(af.z, af.z);
            u64 a3 = pk2(af.w, af.w);
            fma2(acc2[0][0], a0, bv.x); fma2(acc2[0][1], a0, bv.y);
            fma2(acc2[1][0], a1, bv.x); fma2(acc2[1][1], a1, bv.y);
            fma2(acc2[2][0], a2, bv.x); fma2(acc2[2][1], a2, bv.y);
            fma2(acc2[3][0], a3, bv.x); fma2(acc2[3][1], a3, bv.y);
        }
        __syncthreads();
    }

    #pragma unroll
    for (int i = 0; i < 4; i++) {
        float f0, f1, f2, f3;
        upk2(f0, f1, acc2[i][0]);
        upk2(f2, f3, acc2[i][1]);
        *(float4*)&d_kvpart[b][p][(ty * 4 + i) * H2c + tx * 4] =
            make_float4(f0, f1, f2, f3);
    }
}

// ---------------- reduce kv + den partials ----------------
__global__ void __launch_bounds__(256) kB2()
{
    int idx = blockIdx.x * 256 + threadIdx.x;
    if (idx < Bc * Rc * H2c) {
        int b = idx / (Rc * H2c), rc = idx % (Rc * H2c);
        float s = 0.f;
        for (int p = 0; p < PB; p++) s += d_kvpart[b][p][rc];
        d_kv[b][rc] = s;
    } else if (idx < Bc * Rc * H2c + Rc) {
        int r = idx - Bc * Rc * H2c;
        float s = 0.f;
        for (int k = 0; k < DEN_CHUNKS; k++) s += d_denpart[r][k];
        d_denv[r] = s;
    }
}

// ---------------- Stage C: packed-pair numerator + packed out GEMM ----------------
__global__ void __launch_bounds__(128) kC(
    const float* __restrict__ ln_g, const float* __restrict__ ln_b,
    const float* __restrict__ w_reg, const float* __restrict__ b_reg,
    float* __restrict__ out)
{
    int b = blockIdx.y;
    __shared__ u64  s_kv2[Rc * 32];            // kv as f32 pairs
    __shared__ u64  s_wr2[12 * 64];            // w_reg as f32 pairs
    __shared__ float s_den[Rc], s_g[H2c], s_be[H2c], s_br[12];
    int tid = threadIdx.x;
    {
        const ulonglong2* kvsrc = (const ulonglong2*)&d_kv[b][0];
        ulonglong2* kvdst = (ulonglong2*)s_kv2;
        for (int i = tid; i < Rc * 16; i += 128) kvdst[i] = kvsrc[i];
        const ulonglong2* wrsrc = (const ulonglong2*)w_reg;
        ulonglong2* wrdst = (ulonglong2*)s_wr2;
        for (int i = tid; i < 12 * 32; i += 128) wrdst[i] = wrsrc[i];
    }
    if (tid < Rc)  s_den[tid] = d_denv[tid];
    if (tid < H2c) { s_g[tid] = ln_g[tid]; s_be[tid] = ln_b[tid]; }
    if (tid < 12)  s_br[tid] = b_reg[tid];
    __syncthreads();

    int n = blockIdx.x * 128 + tid;
    if (n >= Nc) return;
    int bn = b * Nc + n;

    u64 h2[32];
    #pragma unroll
    for (int c = 0; c < 32; c++) h2[c] = 0ull;
    float den = 0.f;

    #pragma unroll 4
    for (int r = 0; r < Rc; r++) {
        float q = d_qp[r * Nc + n];
        den += q * s_den[r];
        u64 q2 = pk2(q, q);
        const ulonglong2* kvp = (const ulonglong2*)&s_kv2[r * 32];
        #pragma unroll
        for (int c8 = 0; c8 < 16; c8++) {
            ulonglong2 v = kvp[c8];
            fma2(h2[c8 * 2 + 0], q2, v.x);
            fma2(h2[c8 * 2 + 1], q2, v.y);
        }
    }

    float h[H2c];
    #pragma unroll
    for (int c = 0; c < 32; c++) upk2(h[c * 2], h[c * 2 + 1], h2[c]);

    float inv = 1.f / den;
    u64 oacc[12];
    #pragma unroll
    for (int o = 0; o < 12; o++) oacc[o] = 0ull;

    float mu = 0.f;
    // ie part (c = 0..31)
    #pragma unroll
    for (int c4 = 0; c4 < 8; c4++) {
        float v0 = d_ie[(size_t)(c4 * 4 + 0) * BNc + bn];
        float v1 = d_ie[(size_t)(c4 * 4 + 1) * BNc + bn];
        float v2 = d_ie[(size_t)(c4 * 4 + 2) * BNc + bn];
        float v3 = d_ie[(size_t)(c4 * 4 + 3) * BNc + bn];
        h[c4 * 4 + 0] = h[c4 * 4 + 0] * inv + v0; mu += h[c4 * 4 + 0];
        h[c4 * 4 + 1] = h[c4 * 4 + 1] * inv + v1; mu += h[c4 * 4 + 1];
        h[c4 * 4 + 2] = h[c4 * 4 + 2] * inv + v2; mu += h[c4 * 4 + 2];
        h[c4 * 4 + 3] = h[c4 * 4 + 3] * inv + v3; mu += h[c4 * 4 + 3];
        u64 xp01 = pk2(fmaxf(v0, 0.f), fmaxf(v1, 0.f));
        u64 xp23 = pk2(fmaxf(v2, 0.f), fmaxf(v3, 0.f));
        #pragma unroll
        for (int o = 0; o < 12; o++) {
            ulonglong2 w = *(const ulonglong2*)&s_wr2[o * 64 + c4 * 2];
            fma2(oacc[o], xp01, w.x);
            fma2(oacc[o], xp23, w.y);
        }
    }
    // node part (c = 32..63)
    #pragma unroll
    for (int c4 = 8; c4 < 16; c4++) {
        float v0 = d_neT[(c4 * 4 + 0 - Hc) * Nc + n];
        float v1 = d_neT[(c4 * 4 + 1 - Hc) * Nc + n];
        float v2 = d_neT[(c4 * 4 + 2 - Hc) * Nc + n];
        float v3 = d_neT[(c4 * 4 + 3 - Hc) * Nc + n];
        h[c4 * 4 + 0] = h[c4 * 4 + 0] * inv + v0; mu += h[c4 * 4 + 0];
        h[c4 * 4 + 1] = h[c4 * 4 + 1] * inv + v1; mu += h[c4 * 4 + 1];
        h[c4 * 4 + 2] = h[c4 * 4 + 2] * inv + v2; mu += h[c4 * 4 + 2];
        h[c4 * 4 + 3] = h[c4 * 4 + 3] * inv + v3; mu += h[c4 * 4 + 3];
        u64 xp01 = pk2(fmaxf(v0, 0.f), fmaxf(v1, 0.f));
        u64 xp23 = pk2(fmaxf(v2, 0.f), fmaxf(v3, 0.f));
        #pragma unroll
        for (int o = 0; o < 12; o++) {
            ulonglong2 w = *(const ulonglong2*)&s_wr2[o * 64 + c4 * 2];
            fma2(oacc[o], xp01, w.x);
            fma2(oacc[o], xp23, w.y);
        }
    }

    mu *= (1.f / H2c);
    float var = 0.f;
    #pragma unroll
    for (int c = 0; c < H2c; c++) { float d0 = h[c] - mu; var += d0 * d0; }
    var *= (1.f / H2c);
    float rstd = rsqrtf(var + EPS_LN);
    #pragma unroll
    for (int c = 0; c < H2c; c++)
        h[c] = fmaxf((h[c] - mu) * rstd * s_g[c] + s_be[c], 0.f);

    #pragma unroll
    for (int c4 = 0; c4 < 16; c4++) {
        u64 hp01 = pk2(h[c4 * 4 + 0], h[c4 * 4 + 1]);
        u64 hp23 = pk2(h[c4 * 4 + 2], h[c4 * 4 + 3]);
        #pragma unroll
        for (int o = 0; o < 12; o++) {
            ulonglong2 w = *(const ulonglong2*)&s_wr2[o * 64 + 32 + c4 * 2];
            fma2(oacc[o], hp01, w.x);
            fma2(oacc[o], hp23, w.y);
        }
    }

    float* op = out + (size_t)bn * 12;
    #pragma unroll
    for (int o = 0; o < 12; o++) {
        float lo, hi;
        upk2(lo, hi, oacc[o]);
        op[o] = s_br[o] + lo + hi;
    }
}

// ---------------- launch ----------------
extern "C" void kernel_launch(void* const* d_in, const int* in_sizes, int n_in,
                              void* d_out, int out_size)
{
    (void)in_sizes; (void)n_in; (void)out_size;
    const float* x        = (const float*)d_in[0];
    const float* node_emb = (const float*)d_in[1];
    const float* w_input  = (const float*)d_in[4];
    const float* b_input  = (const float*)d_in[5];
    const float* w1       = (const float*)d_in[6];
    const float* b1       = (const float*)d_in[7];
    const float* w2       = (const float*)d_in[8];
    const float* b2       = (const float*)d_in[9];
    const float* fc_w     = (const float*)d_in[14];
    const float* fc_b     = (const float*)d_in[15];
    const float* ln_g     = (const float*)d_in[18];
    const float* ln_b     = (const float*)d_in[19];
    const float* w_reg    = (const float*)d_in[22];
    const float* b_reg    = (const float*)d_in[23];
    const float* rm1      = (const float*)d_in[24];
    float* out = (float*)d_out;

    kInit<<<1, 1>>>();
    kA<<<dim3(NBLK, 2), 128>>>(node_emb, w1, b1, w2, b2, rm1, fc_w, fc_b);
    kKP<<<dim3(DEN_CHUNKS, Rc), 256>>>();
    kV<<<(BNc + 127) / 128, 128>>>(x, w_input, b_input, fc_w);
    kB<<<dim3(PB, Bc), 256>>>();
    kB2<<<(Bc * Rc * H2c + Rc + 255) / 256, 256>>>();
    kC<<<dim3(NBLK, Bc), 128>>>(ln_g, ln_b, w_reg, b_reg, out);
}

// round 9
// speedup vs baseline: 1.1856x; 1.0191x over previous
#include <cuda_runtime.h>
#include <math.h>

// ---------------- problem constants ----------------
#define Bc   4
#define Nc   50000
#define BNc  (Bc * Nc)
#define Tc   12
#define Hc   32
#define H2c  64
#define Rc   64

#define NRM     0.4204482076268573f   /* 32^-0.25 */
#define RATIO   0.125f                /* 64^-0.5  */
#define EPSP    1e-4f
#define EPS_LN  1e-5f

#define PB         391                /* kv partial blocks per batch */
#define CHUNK      128                /* nodes per kv block          */
#define TJ         32                 /* k tile in kv inner loop     */
#define NBLK       391                /* ceil(Nc/128)                */
#define DEN_CHUNKS 196                /* ceil(Nc/256)                */

typedef unsigned long long u64;

// ---------------- f32x2 packed math (Blackwell) ----------------
__device__ __forceinline__ u64 pk2(float a, float b) {
    u64 r;
    asm("mov.b64 %0, {%1, %2};" : "=l"(r) : "f"(a), "f"(b));
    return r;
}
__device__ __forceinline__ void fma2(u64& d, u64 a, u64 b) {
    asm("fma.rn.f32x2 %0, %1, %2, %0;" : "+l"(d) : "l"(a), "l"(b));
}
__device__ __forceinline__ void upk2(float& lo, float& hi, u64 v) {
    asm("mov.b64 {%0, %1}, %2;" : "=f"(lo), "=f"(hi) : "l"(v));
}

// ---------------- scratch ----------------
__device__ float    d_qp[Rc * Nc];
__device__ float    d_fk[Rc * Nc];
__device__ float    d_kp[Rc * Nc];
__device__ float    d_hnode[H2c * Nc];
__device__ float    d_neT[Hc * Nc];
__device__ float    d_h0[H2c * BNc];
__device__ float    d_ie[Hc * BNc];
__device__ unsigned d_keymax;
__device__ float    d_kv[Bc][Rc * H2c];
__device__ float    d_denv[Rc];
__device__ float    d_kvpart[Bc][PB][Rc * H2c];
__device__ float    d_denpart[Rc][DEN_CHUNKS];

__global__ void kInit() { d_keymax = 0u; }

__device__ __forceinline__ float decode_max(unsigned enc) {
    return (enc & 0x80000000u) ? __uint_as_float(enc ^ 0x80000000u)
                               : __uint_as_float(~enc);
}

// ---------------- Stage A: split y=0 queries (smem dd cache) | y=1 keys+hnode ----------------
__global__ void __launch_bounds__(128) kA(
    const float* __restrict__ node_emb,
    const float* __restrict__ w1, const float* __restrict__ b1,
    const float* __restrict__ w2, const float* __restrict__ b2,
    const float* __restrict__ rm1,
    const float* __restrict__ fc_w, const float* __restrict__ fc_b)
{
    __shared__ float sm[11424];
    int tid = threadIdx.x;
    int n = blockIdx.x * 128 + tid;

    if (blockIdx.y == 0) {
        // ---------- queries ----------
        float* s_w1 = sm;            // 1024
        float* s_rm = sm + 1024;     // 2048
        float* s_b1 = sm + 3072;     // 32
        float* s_dd = sm + 3104;     // 64*128 = 8192
        for (int i = tid; i < Hc * Hc; i += 128) s_w1[i] = w1[i];
        for (int i = tid; i < Rc * Hc; i += 128) s_rm[i] = rm1[i];
        if (tid < Hc) s_b1[tid] = b1[tid];
        __syncthreads();
        if (n >= Nc) return;

        float nd[Hc];
        #pragma unroll
        for (int d = 0; d < Hc; d++) nd[d] = node_emb[n * Hc + d];

        float nv[Hc];
        #pragma unroll
        for (int h = 0; h < Hc; h++) {
            float a = s_b1[h];
            #pragma unroll
            for (int d = 0; d < Hc; d++) a += nd[d] * s_w1[h * Hc + d];
            nv[h] = a;
        }
        float diag = 0.f;
        #pragma unroll
        for (int h = 0; h < Hc; h++) diag += nv[h] * nv[h];
        diag *= 0.5f * NRM * NRM;

        float mx = -3.0e38f;
        for (int r = 0; r < Rc; r++) {
            float a = 0.f;
            #pragma unroll
            for (int h = 0; h < Hc; h++) a += nv[h] * s_rm[r * Hc + h];
            a *= NRM;
            s_dd[r * 128 + tid] = a;
            mx = fmaxf(mx, a);
        }
        float base = diag + mx;
        for (int r = 0; r < Rc; r++)
            d_qp[r * Nc + n] = RATIO * (__expf(s_dd[r * 128 + tid] - base) + EPSP);
    } else {
        // ---------- keys + hnode + neT ----------
        float* s_w2 = sm;            // 1024
        float* s_rm = sm + 1024;     // 2048
        float* s_fr = sm + 3072;     // 2048
        float* s_b2 = sm + 5120;     // 32
        float* s_fb = sm + 5152;     // 64
        for (int i = tid; i < Hc * Hc; i += 128) s_w2[i] = w2[i];
        for (int i = tid; i < Rc * Hc; i += 128) s_rm[i] = rm1[i];
        for (int i = tid; i < H2c * Hc; i += 128) {
            int o = i / Hc, d = i % Hc;
            s_fr[i] = fc_w[o * H2c + Hc + d];
        }
        if (tid < Hc)  s_b2[tid] = b2[tid];
        if (tid < H2c) s_fb[tid] = fc_b[tid];
        __syncthreads();

        float kmaxdd = -3.0e38f;
        if (n < Nc) {
            float nd[Hc];
            #pragma unroll
            for (int d = 0; d < Hc; d++) nd[d] = node_emb[n * Hc + d];
            #pragma unroll
            for (int d = 0; d < Hc; d++) d_neT[d * Nc + n] = nd[d];

            float nv[Hc];
            #pragma unroll
            for (int h = 0; h < Hc; h++) {
                float a = s_b2[h];
                #pragma unroll
                for (int d = 0; d < Hc; d++) a += nd[d] * s_w2[h * Hc + d];
                nv[h] = a;
            }
            float diagk = 0.f;
            #pragma unroll
            for (int h = 0; h < Hc; h++) diagk += nv[h] * nv[h];
            diagk *= 0.5f * NRM * NRM;

            for (int r = 0; r < Rc; r++) {
                float a = 0.f;
                #pragma unroll
                for (int h = 0; h < Hc; h++) a += nv[h] * s_rm[r * Hc + h];
                a *= NRM;
                d_fk[r * Nc + n] = a - diagk;
                kmaxdd = fmaxf(kmaxdd, a);
            }

            for (int o = 0; o < H2c; o++) {
                float a = s_fb[o];
                #pragma unroll
                for (int d = 0; d < Hc; d++) a += nd[d] * s_fr[o * Hc + d];
                d_hnode[o * Nc + n] = a;
            }
        }
        #pragma unroll
        for (int off = 16; off; off >>= 1)
            kmaxdd = fmaxf(kmaxdd, __shfl_xor_sync(0xffffffffu, kmaxdd, off));
        if ((tid & 31) == 0) {
            unsigned bits = __float_as_uint(kmaxdd);
            unsigned enc = (bits & 0x80000000u) ? ~bits : (bits | 0x80000000u);
            atomicMax(&d_keymax, enc);
        }
    }
}

// ---------------- kKP: kp = ratio*(exp(fk - M) + eps) once; den partials ----------------
__global__ void __launch_bounds__(256) kKP()
{
    int r = blockIdx.y;
    int n = blockIdx.x * 256 + threadIdx.x;
    float M = decode_max(d_keymax);
    float v = 0.f;
    if (n < Nc) {
        v = RATIO * (__expf(d_fk[r * Nc + n] - M) + EPSP);
        d_kp[r * Nc + n] = v;
    }
    // block reduction for den
    #pragma unroll
    for (int off = 16; off; off >>= 1)
        v += __shfl_xor_sync(0xffffffffu, v, off);
    __shared__ float red[8];
    if ((threadIdx.x & 31) == 0) red[threadIdx.x >> 5] = v;
    __syncthreads();
    if (threadIdx.x < 8) {
        float s = red[threadIdx.x];
        #pragma unroll
        for (int off = 4; off; off >>= 1)
            s += __shfl_xor_sync(0xffu, s, off);
        if (threadIdx.x == 0) d_denpart[r][blockIdx.x] = s;
    }
}

// ---------------- Stage V: packed ie-GEMM + unrolled h0 GEMM, higher occupancy ----------------
__global__ void __launch_bounds__(128, 7) kV(
    const float* __restrict__ x,
    const float* __restrict__ w_input, const float* __restrict__ b_input,
    const float* __restrict__ fc_w)
{
    __shared__ u64   s_wiT[Tc * 16];          // w_input transposed, f32x2 pairs [t][hp]
    __shared__ float s_bi[Hc], s_fl[H2c * Hc];
    int tid = threadIdx.x;
    for (int i = tid; i < Tc * 16; i += 128) {
        int t = i >> 4, hp = i & 15;
        s_wiT[i] = pk2(w_input[(2 * hp) * Tc + t], w_input[(2 * hp + 1) * Tc + t]);
    }
    for (int i = tid; i < H2c * Hc; i += 128) {
        int o = i / Hc, d = i % Hc;
        s_fl[i] = fc_w[o * H2c + d];
    }
    if (tid < Hc) s_bi[tid] = b_input[tid];
    __syncthreads();

    int bn = blockIdx.x * 128 + tid;
    if (bn >= BNc) return;
    int n = bn % Nc;

    const float* xp = x + (size_t)bn * (Tc * 3);
    u64 xt2[Tc];
    #pragma unroll
    for (int t = 0; t < Tc; t++) { float v = xp[t * 3]; xt2[t] = pk2(v, v); }

    u64 ie2[16];
    #pragma unroll
    for (int hp = 0; hp < 16; hp++) {
        u64 acc = pk2(s_bi[2 * hp], s_bi[2 * hp + 1]);
        #pragma unroll
        for (int t = 0; t < Tc; t++) fma2(acc, xt2[t], s_wiT[t * 16 + hp]);
        ie2[hp] = acc;
        float a0, a1;
        upk2(a0, a1, acc);
        d_ie[(size_t)(2 * hp) * BNc + bn] = a0;
        d_ie[(size_t)(2 * hp + 1) * BNc + bn] = a1;
    }

    #pragma unroll 4
    for (int o = 0; o < H2c; o++) {
        float hn = d_hnode[o * Nc + n];
        u64 acc_a = 0ull, acc_b = 0ull;
        const ulonglong2* fl2 = (const ulonglong2*)&s_fl[o * Hc];
        #pragma unroll
        for (int k = 0; k < 8; k++) {
            ulonglong2 f = fl2[k];
            fma2(acc_a, ie2[2 * k + 0], f.x);
            fma2(acc_b, ie2[2 * k + 1], f.y);
        }
        float l0, h0v, l1, h1v;
        upk2(l0, h0v, acc_a);
        upk2(l1, h1v, acc_b);
        float a = hn + ((l0 + h0v) + (l1 + h1v));
        d_h0[(size_t)o * BNc + bn] = fmaxf(a, 0.f);
    }
}

// ---------------- Stage B: outer-product kv partials (pure GEMM) ----------------
__global__ void __launch_bounds__(256) kB()
{
    int b = blockIdx.y, p = blockIdx.x;
    int n0 = p * CHUNK;
    int n1 = min(n0 + CHUNK, Nc);
    int tid = threadIdx.x;
    int ty = tid >> 4;                  // 0..15: r-group (4 rows)
    int tx = tid & 15;                  // 0..15: c-group (4 cols)

    __shared__ float s_a[TJ][68];       // [k][r]  kp
    __shared__ float s_v[TJ][68];       // [k][c]  h0

    u64 acc2[4][2];
    #pragma unroll
    for (int i = 0; i < 4; i++) { acc2[i][0] = 0ull; acc2[i][1] = 0ull; }

    for (int jt = n0; jt < n1; jt += TJ) {
        int cnt = min(TJ, n1 - jt);
        for (int idx = tid; idx < Rc * TJ; idx += 256) {
            int rr = idx >> 5, kk = idx & 31;
            s_a[kk][rr] = (kk < cnt) ? d_kp[rr * Nc + jt + kk] : 0.f;
        }
        for (int idx = tid; idx < H2c * TJ; idx += 256) {
            int cc = idx >> 5, kk = idx & 31;
            s_v[kk][cc] = (kk < cnt)
                ? d_h0[(size_t)cc * BNc + (size_t)b * Nc + jt + kk] : 0.f;
        }
        __syncthreads();

        #pragma unroll 4
        for (int k = 0; k < TJ; k++) {
            float4 af = *(const float4*)&s_a[k][ty * 4];
            ulonglong2 bv = *(const ulonglong2*)&s_v[k][tx * 4];
            u64 a0 = pk2(af.x, af.x);
            u64 a1 = pk2(af.y, af.y);
            u64 a2 = pk2(af.z, af.z);
            u64 a3 = pk2(af.w, af.w);
            fma2(acc2[0][0], a0, bv.x); fma2(acc2[0][1], a0, bv.y);
            fma2(acc2[1][0], a1, bv.x); fma2(acc2[1][1], a1, bv.y);
            fma2(acc2[2][0], a2, bv.x); fma2(acc2[2][1], a2, bv.y);
            fma2(acc2[3][0], a3, bv.x); fma2(acc2[3][1], a3, bv.y);
        }
        __syncthreads();
    }

    #pragma unroll
    for (int i = 0; i < 4; i++) {
        float f0, f1, f2, f3;
        upk2(f0, f1, acc2[i][0]);
        upk2(f2, f3, acc2[i][1]);
        *(float4*)&d_kvpart[b][p][(ty * 4 + i) * H2c + tx * 4] =
            make_float4(f0, f1, f2, f3);
    }
}

// ---------------- reduce kv + den partials ----------------
__global__ void __launch_bounds__(256) kB2()
{
    int idx = blockIdx.x * 256 + threadIdx.x;
    if (idx < Bc * Rc * H2c) {
        int b = idx / (Rc * H2c), rc = idx % (Rc * H2c);
        float s = 0.f;
        for (int p = 0; p < PB; p++) s += d_kvpart[b][p][rc];
        d_kv[b][rc] = s;
    } else if (idx < Bc * Rc * H2c + Rc) {
        int r = idx - Bc * Rc * H2c;
        float s = 0.f;
        for (int k = 0; k < DEN_CHUNKS; k++) s += d_denpart[r][k];
        d_denv[r] = s;
    }
}

// ---------------- Stage C: packed-pair numerator + packed out GEMM ----------------
__global__ void __launch_bounds__(128) kC(
    const float* __restrict__ ln_g, const float* __restrict__ ln_b,
    const float* __restrict__ w_reg, const float* __restrict__ b_reg,
    float* __restrict__ out)
{
    int b = blockIdx.y;
    __shared__ u64  s_kv2[Rc * 32];            // kv as f32 pairs
    __shared__ u64  s_wr2[12 * 64];            // w_reg as f32 pairs
    __shared__ float s_den[Rc], s_g[H2c], s_be[H2c], s_br[12];
    int tid = threadIdx.x;
    {
        const ulonglong2* kvsrc = (const ulonglong2*)&d_kv[b][0];
        ulonglong2* kvdst = (ulonglong2*)s_kv2;
        for (int i = tid; i < Rc * 16; i += 128) kvdst[i] = kvsrc[i];
        const ulonglong2* wrsrc = (const ulonglong2*)w_reg;
        ulonglong2* wrdst = (ulonglong2*)s_wr2;
        for (int i = tid; i < 12 * 32; i += 128) wrdst[i] = wrsrc[i];
    }
    if (tid < Rc)  s_den[tid] = d_denv[tid];
    if (tid < H2c) { s_g[tid] = ln_g[tid]; s_be[tid] = ln_b[tid]; }
    if (tid < 12)  s_br[tid] = b_reg[tid];
    __syncthreads();

    int n = blockIdx.x * 128 + tid;
    if (n >= Nc) return;
    int bn = b * Nc + n;

    u64 h2[32];
    #pragma unroll
    for (int c = 0; c < 32; c++) h2[c] = 0ull;
    float den = 0.f;

    #pragma unroll 4
    for (int r = 0; r < Rc; r++) {
        float q = d_qp[r * Nc + n];
        den += q * s_den[r];
        u64 q2 = pk2(q, q);
        const ulonglong2* kvp = (const ulonglong2*)&s_kv2[r * 32];
        #pragma unroll
        for (int c8 = 0; c8 < 16; c8++) {
            ulonglong2 v = kvp[c8];
            fma2(h2[c8 * 2 + 0], q2, v.x);
            fma2(h2[c8 * 2 + 1], q2, v.y);
        }
    }

    float h[H2c];
    #pragma unroll
    for (int c = 0; c < 32; c++) upk2(h[c * 2], h[c * 2 + 1], h2[c]);

    float inv = 1.f / den;
    u64 oacc[12];
    #pragma unroll
    for (int o = 0; o < 12; o++) oacc[o] = 0ull;

    float mu = 0.f;
    // ie part (c = 0..31)
    #pragma unroll
    for (int c4 = 0; c4 < 8; c4++) {
        float v0 = d_ie[(size_t)(c4 * 4 + 0) * BNc + bn];
        float v1 = d_ie[(size_t)(c4 * 4 + 1) * BNc + bn];
        float v2 = d_ie[(size_t)(c4 * 4 + 2) * BNc + bn];
        float v3 = d_ie[(size_t)(c4 * 4 + 3) * BNc + bn];
        h[c4 * 4 + 0] = h[c4 * 4 + 0] * inv + v0; mu += h[c4 * 4 + 0];
        h[c4 * 4 + 1] = h[c4 * 4 + 1] * inv + v1; mu += h[c4 * 4 + 1];
        h[c4 * 4 + 2] = h[c4 * 4 + 2] * inv + v2; mu += h[c4 * 4 + 2];
        h[c4 * 4 + 3] = h[c4 * 4 + 3] * inv + v3; mu += h[c4 * 4 + 3];
        u64 xp01 = pk2(fmaxf(v0, 0.f), fmaxf(v1, 0.f));
        u64 xp23 = pk2(fmaxf(v2, 0.f), fmaxf(v3, 0.f));
        #pragma unroll
        for (int o = 0; o < 12; o++) {
            ulonglong2 w = *(const ulonglong2*)&s_wr2[o * 64 + c4 * 2];
            fma2(oacc[o], xp01, w.x);
            fma2(oacc[o], xp23, w.y);
        }
    }
    // node part (c = 32..63)
    #pragma unroll
    for (int c4 = 8; c4 < 16; c4++) {
        float v0 = d_neT[(c4 * 4 + 0 - Hc) * Nc + n];
        float v1 = d_neT[(c4 * 4 + 1 - Hc) * Nc + n];
        float v2 = d_neT[(c4 * 4 + 2 - Hc) * Nc + n];
        float v3 = d_neT[(c4 * 4 + 3 - Hc) * Nc + n];
        h[c4 * 4 + 0] = h[c4 * 4 + 0] * inv + v0; mu += h[c4 * 4 + 0];
        h[c4 * 4 + 1] = h[c4 * 4 + 1] * inv + v1; mu += h[c4 * 4 + 1];
        h[c4 * 4 + 2] = h[c4 * 4 + 2] * inv + v2; mu += h[c4 * 4 + 2];
        h[c4 * 4 + 3] = h[c4 * 4 + 3] * inv + v3; mu += h[c4 * 4 + 3];
        u64 xp01 = pk2(fmaxf(v0, 0.f), fmaxf(v1, 0.f));
        u64 xp23 = pk2(fmaxf(v2, 0.f), fmaxf(v3, 0.f));
        #pragma unroll
        for (int o = 0; o < 12; o++) {
            ulonglong2 w = *(const ulonglong2*)&s_wr2[o * 64 + c4 * 2];
            fma2(oacc[o], xp01, w.x);
            fma2(oacc[o], xp23, w.y);
        }
    }

    mu *= (1.f / H2c);
    float var = 0.f;
    #pragma unroll
    for (int c = 0; c < H2c; c++) { float d0 = h[c] - mu; var += d0 * d0; }
    var *= (1.f / H2c);
    float rstd = rsqrtf(var + EPS_LN);
    #pragma unroll
    for (int c = 0; c < H2c; c++)
        h[c] = fmaxf((h[c] - mu) * rstd * s_g[c] + s_be[c], 0.f);

    #pragma unroll
    for (int c4 = 0; c4 < 16; c4++) {
        u64 hp01 = pk2(h[c4 * 4 + 0], h[c4 * 4 + 1]);
        u64 hp23 = pk2(h[c4 * 4 + 2], h[c4 * 4 + 3]);
        #pragma unroll
        for (int o = 0; o < 12; o++) {
            ulonglong2 w = *(const ulonglong2*)&s_wr2[o * 64 + 32 + c4 * 2];
            fma2(oacc[o], hp01, w.x);
            fma2(oacc[o], hp23, w.y);
        }
    }

    float* op = out + (size_t)bn * 12;
    #pragma unroll
    for (int o = 0; o < 12; o++) {
        float lo, hi;
        upk2(lo, hi, oacc[o]);
        op[o] = s_br[o] + lo + hi;
    }
}

// ---------------- launch ----------------
extern "C" void kernel_launch(void* const* d_in, const int* in_sizes, int n_in,
                              void* d_out, int out_size)
{
    (void)in_sizes; (void)n_in; (void)out_size;
    const float* x        = (const float*)d_in[0];
    const float* node_emb = (const float*)d_in[1];
    const float* w_input  = (const float*)d_in[4];
    const float* b_input  = (const float*)d_in[5];
    const float* w1       = (const float*)d_in[6];
    const float* b1       = (const float*)d_in[7];
    const float* w2       = (const float*)d_in[8];
    const float* b2       = (const float*)d_in[9];
    const float* fc_w     = (const float*)d_in[14];
    const float* fc_b     = (const float*)d_in[15];
    const float* ln_g     = (const float*)d_in[18];
    const float* ln_b     = (const float*)d_in[19];
    const float* w_reg    = (const float*)d_in[22];
    const float* b_reg    = (const float*)d_in[23];
    const float* rm1      = (const float*)d_in[24];
    float* out = (float*)d_out;

    kInit<<<1, 1>>>();
    kA<<<dim3(NBLK, 2), 128>>>(node_emb, w1, b1, w2, b2, rm1, fc_w, fc_b);
    kKP<<<dim3(DEN_CHUNKS, Rc), 256>>>();
    kV<<<(BNc + 127) / 128, 128>>>(x, w_input, b_input, fc_w);
    kB<<<dim3(PB, Bc), 256>>>();
    kB2<<<(Bc * Rc * H2c + Rc + 255) / 256, 256>>>();
    kC<<<dim3(NBLK, Bc), 128>>>(ln_g, ln_b, w_reg, b_reg, out);
}